// round 5
// baseline (speedup 1.0000x reference)
#include <cuda_runtime.h>
#include <math.h>

// ---------------------------------------------------------------------------
// Problem constants
// ---------------------------------------------------------------------------
#define BATCH    128
#define LATENT   256
#define HIDDEN   512
#define MNODES   64
#define NPAIRS   2016           // 64*63/2
#define G3       (3*HIDDEN)     // 1536

// ---------------------------------------------------------------------------
// Device scratch (no cudaMalloc allowed)
// ---------------------------------------------------------------------------
__device__ float g_Cm  [MNODES * LATENT];          // C[t][l]
__device__ float g_zWT [LATENT * BATCH];           // zW^T [l][b]
__device__ float g_AT  [G3 * BATCH];               // A^T  [g][b]
__device__ float g_D   [MNODES * G3];              // D    [t][g]
__device__ float g_P   [HIDDEN * HIDDEN];          // adj_W1a @ node_W
__device__ float g_Q   [HIDDEN * HIDDEN];          // adj_W1b @ node_W
__device__ float g_gh  [G3 * BATCH];               // recurrent GEMM out [g][b]
__device__ float g_h1T [MNODES * HIDDEN * BATCH];  // layer-0 hidden [t][k][b]
__device__ float g_h2T [MNODES * HIDDEN * BATCH];  // layer-1 hidden [t][k][b]
__device__ float g_gi1 [MNODES * G3 * BATCH];      // layer-1 input proj [t][g][b]
__device__ float g_U   [BATCH * MNODES * HIDDEN];  // [b][t][h]
__device__ float g_V   [BATCH * MNODES * HIDDEN];  // [b][t][h] (+adj_b1)
__device__ int   g_ii  [NPAIRS];
__device__ int   g_jj  [NPAIRS];

// ---------------------------------------------------------------------------
// Generic tiled fp32 GEMM:  C[m][n] = sum_k A(m,k) * B(n,k)  (+ bias[n])
//  A_ROW : A stored row-major (M x K, lda) else K-major (K x M, lda)
//  B_NK  : B stored (N x K, ldb) else (K x N, ldb)
//  C row-major with ldc. blockIdx.z batching via aZ/bZ/cZ element strides.
// ---------------------------------------------------------------------------
template<int BM, int BN, int BK, int TM, int TN, bool A_ROW, bool B_NK>
__global__ void sgemm_k(const float* __restrict__ Ag, const float* __restrict__ Bg,
                        float* __restrict__ Cg, const float* __restrict__ bias,
                        int K, int lda, int ldb, int ldc,
                        long aZ, long bZ, long cZ)
{
    const float* A = Ag + (long)blockIdx.z * aZ;
    const float* B = Bg + (long)blockIdx.z * bZ;
    float*       C = Cg + (long)blockIdx.z * cZ;

    __shared__ float As[BK][BM];
    __shared__ float Bs[BK][BN];

    constexpr int NTH = (BM / TM) * (BN / TN);
    const int tid  = threadIdx.x;
    const int tcol = tid % (BN / TN);
    const int trow = tid / (BN / TN);
    const int m0   = blockIdx.y * BM;
    const int n0   = blockIdx.x * BN;

    float acc[TM][TN];
#pragma unroll
    for (int i = 0; i < TM; i++)
#pragma unroll
        for (int j = 0; j < TN; j++) acc[i][j] = 0.f;

    for (int k0 = 0; k0 < K; k0 += BK) {
#pragma unroll
        for (int idx = tid; idx < BM * BK; idx += NTH) {
            int m = idx / BK, kk = idx % BK;
            As[kk][m] = A_ROW ? A[(long)(m0 + m) * lda + (k0 + kk)]
                              : A[(long)(k0 + kk) * lda + (m0 + m)];
        }
#pragma unroll
        for (int idx = tid; idx < BK * BN; idx += NTH) {
            int kk = idx / BN, n = idx % BN;
            Bs[kk][n] = B_NK ? B[(long)(n0 + n) * ldb + (k0 + kk)]
                             : B[(long)(k0 + kk) * ldb + (n0 + n)];
        }
        __syncthreads();
#pragma unroll
        for (int kk = 0; kk < BK; kk++) {
            float a[TM], b[TN];
#pragma unroll
            for (int i = 0; i < TM; i++) a[i] = As[kk][trow * TM + i];
#pragma unroll
            for (int j = 0; j < TN; j++) b[j] = Bs[kk][tcol * TN + j];
#pragma unroll
            for (int i = 0; i < TM; i++)
#pragma unroll
                for (int j = 0; j < TN; j++)
                    acc[i][j] = fmaf(a[i], b[j], acc[i][j]);
        }
        __syncthreads();
    }

#pragma unroll
    for (int i = 0; i < TM; i++) {
        int m = m0 + trow * TM + i;
#pragma unroll
        for (int j = 0; j < TN; j++) {
            int n = n0 + tcol * TN + j;
            float v = acc[i][j];
            if (bias) v += bias[n];
            C[(long)m * ldc + n] = v;
        }
    }
}

// ---------------------------------------------------------------------------
// Small precompute kernels
// ---------------------------------------------------------------------------
__global__ void precompC_k(const float* __restrict__ pe, const float* __restrict__ emb,
                           const float* __restrict__ W_pre, const float* __restrict__ b_pre)
{
    int t = blockIdx.x, l = threadIdx.x;
    const float* w = W_pre + l * 512;
    float acc = b_pre[l];
    for (int d = 0; d < 256; d++)
        acc += pe[t * 256 + d] * w[d] + emb[t * 256 + d] * w[256 + d];
    g_Cm[t * 256 + l] = acc;
}

__global__ void precompzW_k(const float* __restrict__ z, const float* __restrict__ W_pre)
{
    int b = blockIdx.x, l = threadIdx.x;
    const float* w = W_pre + l * 512;
    float acc = 0.f;
    for (int d = 0; d < 256; d++)
        acc += z[b * 256 + d] * w[d];
    g_zWT[l * BATCH + b] = acc;
}

__global__ void pairidx_k()
{
    int p = blockIdx.x * blockDim.x + threadIdx.x;
    if (p >= NPAIRS) return;
    int i = 0, rem = p;
    while (rem >= 63 - i) { rem -= 63 - i; i++; }
    g_ii[p] = i;
    g_jj[p] = i + 1 + rem;
}

__global__ void zero_k(float* p, int n)
{
    int i = blockIdx.x * blockDim.x + threadIdx.x;
    if (i < n) p[i] = 0.f;
}

// ---------------------------------------------------------------------------
// GRU gate kernels. gh (no bias) laid out [g][b]; hidden seq [t][k][b].
// ---------------------------------------------------------------------------
__device__ __forceinline__ float sigm(float x) { return 1.f / (1.f + expf(-x)); }

__global__ void gate0_k(const float* __restrict__ bih, const float* __restrict__ bhh,
                        const int* __restrict__ n_nodes, int t, int first)
{
    int idx = blockIdx.x * blockDim.x + threadIdx.x;   // 65536
    int b = idx & (BATCH - 1);
    int j = idx >> 7;

    float ghr = 0.f, ghz = 0.f, ghn = 0.f, hprev = 0.f;
    if (!first) {
        ghr = g_gh[j * BATCH + b];
        ghz = g_gh[(HIDDEN + j) * BATCH + b];
        ghn = g_gh[(2 * HIDDEN + j) * BATCH + b];
        hprev = g_h1T[((long)(t - 1) * HIDDEN + j) * BATCH + b];
    }
    float gir = bih[j], giz = bih[HIDDEN + j], gin = bih[2 * HIDDEN + j];
    if (t < n_nodes[b]) {
        gir += g_AT[j * BATCH + b]                + g_D[t * G3 + j];
        giz += g_AT[(HIDDEN + j) * BATCH + b]     + g_D[t * G3 + HIDDEN + j];
        gin += g_AT[(2 * HIDDEN + j) * BATCH + b] + g_D[t * G3 + 2 * HIDDEN + j];
    }
    ghr += bhh[j]; ghz += bhh[HIDDEN + j]; ghn += bhh[2 * HIDDEN + j];

    float r  = sigm(gir + ghr);
    float zg = sigm(giz + ghz);
    float n  = tanhf(gin + r * ghn);
    float h  = (1.f - zg) * n + zg * hprev;
    g_h1T[((long)t * HIDDEN + j) * BATCH + b] = h;
}

__global__ void gate1_k(const float* __restrict__ bih, const float* __restrict__ bhh,
                        int t, int first)
{
    int idx = blockIdx.x * blockDim.x + threadIdx.x;
    int b = idx & (BATCH - 1);
    int j = idx >> 7;

    float ghr = 0.f, ghz = 0.f, ghn = 0.f, hprev = 0.f;
    if (!first) {
        ghr = g_gh[j * BATCH + b];
        ghz = g_gh[(HIDDEN + j) * BATCH + b];
        ghn = g_gh[(2 * HIDDEN + j) * BATCH + b];
        hprev = g_h2T[((long)(t - 1) * HIDDEN + j) * BATCH + b];
    }
    const float* gi = g_gi1 + (long)t * G3 * BATCH;
    float gir = gi[j * BATCH + b]                + bih[j];
    float giz = gi[(HIDDEN + j) * BATCH + b]     + bih[HIDDEN + j];
    float gin = gi[(2 * HIDDEN + j) * BATCH + b] + bih[2 * HIDDEN + j];
    ghr += bhh[j]; ghz += bhh[HIDDEN + j]; ghn += bhh[2 * HIDDEN + j];

    float r  = sigm(gir + ghr);
    float zg = sigm(giz + ghz);
    float n  = tanhf(gin + r * ghn);
    float h  = (1.f - zg) * n + zg * hprev;
    g_h2T[((long)t * HIDDEN + j) * BATCH + b] = h;
}

// ---------------------------------------------------------------------------
// Pair kernel: logits + Gumbel hard decision -> writes 1s into zeroed adj.
//   hmid = relu(U[b,i] + V[b,j])   (V already has adj_b1 folded in)
//   l0 = hmid . W2[0] + b2[0] ; l1 = hmid . W2[1] + b2[1]
//   adj[b,i,j] = adj[b,j,i] = (l0+g0 >= l1+g1)
// grid (128, 2), 256 threads (8 warps): warp per pair, strided.
// ---------------------------------------------------------------------------
__global__ void pair_k(const float* __restrict__ W2, const float* __restrict__ b2,
                       const float* __restrict__ gu, const int* __restrict__ n_nodes,
                       float* __restrict__ out)
{
    int b    = blockIdx.x;
    int warp = (int)(blockIdx.y * 8 + (threadIdx.x >> 5));
    int lane = threadIdx.x & 31;
    int nb   = n_nodes[b];
    float* ob = out + (long)b * (MNODES * MNODES);

    float4 w2a[4], w2b[4];
#pragma unroll
    for (int q = 0; q < 4; q++) {
        w2a[q] = *(const float4*)(W2 + 4 * lane + 128 * q);
        w2b[q] = *(const float4*)(W2 + HIDDEN + 4 * lane + 128 * q);
    }

    for (int p = warp; p < NPAIRS; p += 16) {
        int j = g_jj[p];
        if (j >= nb) continue;           // i<j, so j<nb implies i<nb
        int i = g_ii[p];
        const float* Ui = g_U + ((long)b * MNODES + i) * HIDDEN;
        const float* Vj = g_V + ((long)b * MNODES + j) * HIDDEN;
        float a0 = 0.f, a1 = 0.f;
#pragma unroll
        for (int q = 0; q < 4; q++) {
            float4 u = *(const float4*)(Ui + 4 * lane + 128 * q);
            float4 v = *(const float4*)(Vj + 4 * lane + 128 * q);
            float m;
            m = fmaxf(u.x + v.x, 0.f); a0 = fmaf(m, w2a[q].x, a0); a1 = fmaf(m, w2b[q].x, a1);
            m = fmaxf(u.y + v.y, 0.f); a0 = fmaf(m, w2a[q].y, a0); a1 = fmaf(m, w2b[q].y, a1);
            m = fmaxf(u.z + v.z, 0.f); a0 = fmaf(m, w2a[q].z, a0); a1 = fmaf(m, w2b[q].z, a1);
            m = fmaxf(u.w + v.w, 0.f); a0 = fmaf(m, w2a[q].w, a0); a1 = fmaf(m, w2b[q].w, a1);
        }
#pragma unroll
        for (int s = 16; s > 0; s >>= 1) {
            a0 += __shfl_xor_sync(0xffffffffu, a0, s);
            a1 += __shfl_xor_sync(0xffffffffu, a1, s);
        }
        if (lane == 0) {
            float l0 = a0 + b2[0];
            float l1 = a1 + b2[1];
            const float* g = gu + ((long)b * NPAIRS + p) * 2;
            float g0 = -logf(-logf(g[0] + 1e-10f) + 1e-10f);
            float g1 = -logf(-logf(g[1] + 1e-10f) + 1e-10f);
            if (l0 + g0 >= l1 + g1) {
                ob[i * MNODES + j] = 1.f;
                ob[j * MNODES + i] = 1.f;
            }
        }
    }
}

// ---------------------------------------------------------------------------
// Host launch sequence (graph-capturable: kernel launches only)
// ---------------------------------------------------------------------------
extern "C" void kernel_launch(void* const* d_in, const int* in_sizes, int n_in,
                              void* d_out, int out_size)
{
    const float* z       = (const float*)d_in[0];
    const int*   n_nodes = (const int*)  d_in[1];
    /* d_in[2] = n_edges (unused) */
    const float* gu      = (const float*)d_in[3];
    const float* emb     = (const float*)d_in[4];
    const float* pe      = (const float*)d_in[5];
    const float* W_pre   = (const float*)d_in[6];
    const float* b_pre   = (const float*)d_in[7];
    const float* Wih0    = (const float*)d_in[8];
    const float* Whh0    = (const float*)d_in[9];
    const float* bih0    = (const float*)d_in[10];
    const float* bhh0    = (const float*)d_in[11];
    const float* Wih1    = (const float*)d_in[12];
    const float* Whh1    = (const float*)d_in[13];
    const float* bih1    = (const float*)d_in[14];
    const float* bhh1    = (const float*)d_in[15];
    /* node_W */
    const float* node_W  = (const float*)d_in[16];
    const float* adj_W1  = (const float*)d_in[17];
    const float* adj_b1  = (const float*)d_in[18];
    const float* adj_W2  = (const float*)d_in[19];
    const float* adj_b2  = (const float*)d_in[20];
    float* out = (float*)d_out;

    // Resolve device-global scratch addresses
    float *Cm, *zWT, *AT, *D, *P, *Q, *gh, *h1T, *h2T, *gi1, *U, *V;
    cudaGetSymbolAddress((void**)&Cm,  g_Cm);
    cudaGetSymbolAddress((void**)&zWT, g_zWT);
    cudaGetSymbolAddress((void**)&AT,  g_AT);
    cudaGetSymbolAddress((void**)&D,   g_D);
    cudaGetSymbolAddress((void**)&P,   g_P);
    cudaGetSymbolAddress((void**)&Q,   g_Q);
    cudaGetSymbolAddress((void**)&gh,  g_gh);
    cudaGetSymbolAddress((void**)&h1T, g_h1T);
    cudaGetSymbolAddress((void**)&h2T, g_h2T);
    cudaGetSymbolAddress((void**)&gi1, g_gi1);
    cudaGetSymbolAddress((void**)&U,   g_U);
    cudaGetSymbolAddress((void**)&V,   g_V);

    // --- precompute -------------------------------------------------------
    pairidx_k<<<8, 256>>>();
    precompC_k<<<MNODES, 256>>>(pe, emb, W_pre, b_pre);
    precompzW_k<<<BATCH, 256>>>(z, W_pre);

    // AT[g][b] = zW @ Wih0.T, transposed:  M=1536(g), N=128(b), K=256
    sgemm_k<64, 32, 16, 4, 2, true, false><<<dim3(BATCH / 32, G3 / 64), 256>>>(
        Wih0, zWT, AT, nullptr, LATENT, LATENT, BATCH, BATCH, 0, 0, 0);

    // D[t][g] = Cm @ Wih0.T : M=64, N=1536, K=256
    sgemm_k<64, 64, 16, 4, 4, true, true><<<dim3(G3 / 64, 1), 256>>>(
        Cm, Wih0, D, nullptr, LATENT, LATENT, LATENT, G3, 0, 0, 0);

    // P = adj_W1[:, :512] @ node_W  and  Q = adj_W1[:, 512:] @ node_W  (512x512, K=512)
    sgemm_k<64, 64, 16, 4, 4, true, false><<<dim3(8, 8), 256>>>(
        adj_W1, node_W, P, nullptr, HIDDEN, 2 * HIDDEN, HIDDEN, HIDDEN, 0, 0, 0);
    sgemm_k<64, 64, 16, 4, 4, true, false><<<dim3(8, 8), 256>>>(
        adj_W1 + HIDDEN, node_W, Q, nullptr, HIDDEN, 2 * HIDDEN, HIDDEN, HIDDEN, 0, 0, 0);

    // --- GRU layer 0 (sequential) ----------------------------------------
    for (int t = 0; t < MNODES; t++) {
        if (t > 0) {
            // gh[g][b] = Whh0 @ h_prev : M=1536, N=128, K=512
            sgemm_k<64, 32, 16, 4, 2, true, false><<<dim3(BATCH / 32, G3 / 64), 256>>>(
                Whh0, h1T + (long)(t - 1) * HIDDEN * BATCH, gh, nullptr,
                HIDDEN, HIDDEN, BATCH, BATCH, 0, 0, 0);
        }
        gate0_k<<<256, 256>>>(bih0, bhh0, n_nodes, t, t == 0);
    }

    // gi1[t][g][b] = Wih1 @ h1[t] : batched over t (z=64)
    sgemm_k<64, 64, 16, 4, 4, true, false><<<dim3(BATCH / 64, G3 / 64, MNODES), 256>>>(
        Wih1, h1T, gi1, nullptr, HIDDEN, HIDDEN, BATCH, BATCH,
        0, (long)HIDDEN * BATCH, (long)G3 * BATCH);

    // --- GRU layer 1 (sequential) ----------------------------------------
    for (int t = 0; t < MNODES; t++) {
        if (t > 0) {
            sgemm_k<64, 32, 16, 4, 2, true, false><<<dim3(BATCH / 32, G3 / 64), 256>>>(
                Whh1, h2T + (long)(t - 1) * HIDDEN * BATCH, gh, nullptr,
                HIDDEN, HIDDEN, BATCH, BATCH, 0, 0, 0);
        }
        gate1_k<<<256, 256>>>(bih1, bhh1, t, t == 0);
    }

    // --- U / V : batched over t, A is K-major (h2T[t] is [k][b]) ----------
    // U[b][t][h] = h2[t] @ P.T : M=128(b), N=512(h), K=512
    sgemm_k<64, 64, 16, 4, 4, false, true><<<dim3(HIDDEN / 64, BATCH / 64, MNODES), 256>>>(
        h2T, P, U, nullptr, HIDDEN, BATCH, HIDDEN, MNODES * HIDDEN,
        (long)HIDDEN * BATCH, 0, (long)HIDDEN);
    sgemm_k<64, 64, 16, 4, 4, false, true><<<dim3(HIDDEN / 64, BATCH / 64, MNODES), 256>>>(
        h2T, Q, V, adj_b1, HIDDEN, BATCH, HIDDEN, MNODES * HIDDEN,
        (long)HIDDEN * BATCH, 0, (long)HIDDEN);

    // --- output -----------------------------------------------------------
    zero_k<<<(BATCH * MNODES * MNODES + 255) / 256, 256>>>(out, BATCH * MNODES * MNODES);
    pair_k<<<dim3(BATCH, 2), 256>>>(adj_W2, adj_b2, gu, n_nodes, out);
}

// round 6
// speedup vs baseline: 2.0032x; 2.0032x over previous
#include <cuda_runtime.h>
#include <math.h>

#define BATCH  128
#define LATENT 256
#define HIDDEN 512
#define MNODES 64
#define NPAIRS 2016
#define G3     1536
#define HB     65536

typedef unsigned long long u64;

// ---------------- device scratch (no cudaMalloc allowed) -------------------
__device__ __align__(16) float g_Cm [MNODES*LATENT];
__device__ __align__(16) float g_zWT[LATENT*BATCH];
__device__ __align__(16) float g_AT [G3*BATCH];        // [g][b]
__device__ __align__(16) float g_D  [MNODES*G3];       // [t][g]
__device__ __align__(16) float g_P  [HIDDEN*HIDDEN];
__device__ __align__(16) float g_Q  [HIDDEN*HIDDEN];
__device__ __align__(16) float g_h1T[MNODES*HB];       // [t][k][b]
__device__ __align__(16) float g_h2T[MNODES*HB];       // [t][k][b]
__device__ __align__(16) float g_U  [BATCH*MNODES*HIDDEN];
__device__ __align__(16) float g_V  [BATCH*MNODES*HIDDEN];
__device__ int g_ii[NPAIRS];
__device__ int g_jj[NPAIRS];
__device__ unsigned g_bar_cnt;
__device__ unsigned g_bar_gen;

// ---------------- f32x2 helpers (lanes = independent IEEE fma chains) ------
__device__ __forceinline__ u64 pack2(float x){u64 r;asm("mov.b64 %0,{%1,%1};":"=l"(r):"f"(x));return r;}
__device__ __forceinline__ void fma2(u64&a,u64 b,u64 c){asm("fma.rn.f32x2 %0, %1, %2, %0;":"+l"(a):"l"(b),"l"(c));}
__device__ __forceinline__ float2 unpk(u64 v){float2 f;asm("mov.b64 {%0,%1},%2;":"=f"(f.x),"=f"(f.y):"l"(v));return f;}
__device__ __forceinline__ float sigm(float x){return 1.f/(1.f+expf(-x));}

// ---------------- grid barrier (cumulative count; reset kernel per replay) -
__global__ void reset_bar_k(){ g_bar_cnt = 0u; g_bar_gen = 0u; }

__device__ __forceinline__ void gridbar(int call)
{
    __syncthreads();
    if (threadIdx.x == 0) {
        __threadfence();
        unsigned prev = atomicAdd(&g_bar_cnt, 1u);
        if (prev == (unsigned)(call * 128 - 1)) {
            atomicExch(&g_bar_gen, (unsigned)call);
        } else {
            while (*(volatile unsigned*)&g_bar_gen < (unsigned)call) {}
        }
        __threadfence();
    }
    __syncthreads();
}

// ---------------- fused-GRU inner product: 3 gate rows x 2 b-pairs ---------
// w: smem row base for this jj (gates at +4096,+8192), k-chunk already added.
// sH: staged h chunk [128 k][128 b]. acc[x*3+g], x = b-pair index.
__device__ __forceinline__ void chunk3(const float* w, const float* sH, int b0, u64 acc[6])
{
#pragma unroll 2
    for (int k = 0; k < 128; k += 4) {
        float4 w0 = *(const float4*)(w + k);
        float4 w1 = *(const float4*)(w + 4096 + k);
        float4 w2 = *(const float4*)(w + 8192 + k);
        const float* p0 = (const float*)&w0;
        const float* p1 = (const float*)&w1;
        const float* p2 = (const float*)&w2;
#pragma unroll
        for (int q = 0; q < 4; q++) {
            u64 d0 = pack2(p0[q]), d1 = pack2(p1[q]), d2 = pack2(p2[q]);
            const float* hr = sH + (k + q) * 128 + b0;
            u64 h0 = *(const u64*)hr;
            u64 h1 = *(const u64*)(hr + 2);
            fma2(acc[0], d0, h0); fma2(acc[1], d1, h0); fma2(acc[2], d2, h0);
            fma2(acc[3], d0, h1); fma2(acc[4], d1, h1); fma2(acc[5], d2, h1);
        }
    }
}

#define UNPK6(A, R, Z, N) { float2 p; \
    p=unpk(A[0]); R[0]=p.x; R[1]=p.y; p=unpk(A[3]); R[2]=p.x; R[3]=p.y; \
    p=unpk(A[1]); Z[0]=p.x; Z[1]=p.y; p=unpk(A[4]); Z[2]=p.x; Z[3]=p.y; \
    p=unpk(A[2]); N[0]=p.x; N[1]=p.y; p=unpk(A[5]); N[2]=p.x; N[3]=p.y; }

// ---------------- persistent fused 2-layer GRU -----------------------------
// 128 CTAs x 256 thr. CTA: mat = bx&1 (0: layer0 rows, 1: layer1 rows),
// j-chunk j0 = (bx>>1)*8. Thread: bq=tid&31 -> b0=4*bq (4 b), rg=tid>>5 -> j=j0+rg.
// Smem: sW 48KB (Whh rows), sWi 48KB (Wih1 rows, mat1), sH 64KB (h chunk).
__global__ void __launch_bounds__(256, 1)
rnn_fused(const float* __restrict__ Whh0, const float* __restrict__ Whh1,
          const float* __restrict__ Wih1,
          const float* __restrict__ bih0, const float* __restrict__ bhh0,
          const float* __restrict__ bih1, const float* __restrict__ bhh1,
          const int* __restrict__ n_nodes)
{
    extern __shared__ float sm[];
    float* sW  = sm;
    float* sWi = sm + 12288;
    float* sH  = sm + 24576;

    const int tid = threadIdx.x;
    const int mat = blockIdx.x & 1;
    const int j0  = (blockIdx.x >> 1) * 8;
    const int bq  = tid & 31;
    const int rg  = tid >> 5;
    const int b0  = bq * 4;
    const int j   = j0 + rg;

    const float* Wrec = mat ? Whh1 : Whh0;
    for (int i = tid; i < 24 * 128; i += 256) {
        int r = i >> 7, c = i & 127;
        size_t grow = (size_t)((r >> 3) * 512 + j0 + (r & 7)) * 512;
        ((float4*)sW)[i] = *(const float4*)(Wrec + grow + c * 4);
        if (mat) ((float4*)sWi)[i] = *(const float4*)(Wih1 + grow + c * 4);
    }

    float biR, biZ, biN, bhR, bhZ, bhN;
    float4 atR, atZ, atN; int4 nn = make_int4(0,0,0,0);
    if (mat == 0) {
        biR = bih0[j]; biZ = bih0[512+j]; biN = bih0[1024+j];
        bhR = bhh0[j]; bhZ = bhh0[512+j]; bhN = bhh0[1024+j];
        atR = *(const float4*)(g_AT + (size_t)j*128 + b0);
        atZ = *(const float4*)(g_AT + (size_t)(512+j)*128 + b0);
        atN = *(const float4*)(g_AT + (size_t)(1024+j)*128 + b0);
        nn  = *(const int4*)(n_nodes + b0);
    } else {
        biR = bih1[j]; biZ = bih1[512+j]; biN = bih1[1024+j];
        bhR = bhh1[j]; bhZ = bhh1[512+j]; bhN = bhh1[1024+j];
        atR = atZ = atN = make_float4(0,0,0,0);
    }
    float hp[4] = {0.f, 0.f, 0.f, 0.f};   // persistent hidden at (j, b0..b0+3)

    for (int t = 0; t < MNODES; t++) {
        // ---------- phase A: gh = Whh @ h(prev) --------------------------
        u64 accA[6] = {0,0,0,0,0,0};
        if (t > 0) {
            const float* hsrc = (mat ? g_h2T : g_h1T) + (size_t)(t-1)*HB;
            for (int kc = 0; kc < 4; kc++) {
                __syncthreads();
                const float4* s4 = (const float4*)(hsrc + kc*16384);
                float4* d4 = (float4*)sH;
#pragma unroll
                for (int i2 = 0; i2 < 16; i2++)
                    d4[tid + 256*i2] = __ldcg(s4 + tid + 256*i2);
                __syncthreads();
                chunk3(sW + rg*512 + kc*128, sH, b0, accA);
            }
        }

        if (mat == 0) {   // gate0 -> h1[t]
            float ghr[4], ghz[4], ghn[4];
            UNPK6(accA, ghr, ghz, ghn);
            float dR = __ldg(g_D + (size_t)t*G3 + j);
            float dZ = __ldg(g_D + (size_t)t*G3 + 512 + j);
            float dN = __ldg(g_D + (size_t)t*G3 + 1024 + j);
            const float* aR=(const float*)&atR; const float* aZ=(const float*)&atZ;
            const float* aN=(const float*)&atN; const int* nv=(const int*)&nn;
            float4 hnew; float* hv = (float*)&hnew;
#pragma unroll
            for (int i = 0; i < 4; i++) {
                float gir = biR, giz = biZ, gin = biN;
                if (t < nv[i]) { gir += aR[i]+dR; giz += aZ[i]+dZ; gin += aN[i]+dN; }
                float R = ghr[i]+bhR, Z = ghz[i]+bhZ, N = ghn[i]+bhN;
                float r = sigm(gir+R), zg = sigm(giz+Z), nvl = tanhf(gin + r*N);
                float h = (1.f - zg)*nvl + zg*hp[i];
                hp[i] = h; hv[i] = h;
            }
            *(float4*)(g_h1T + (size_t)t*HB + (size_t)j*128 + b0) = hnew;
        }
        gridbar(2*t + 1);

        // ---------- phase B: gi1 = Wih1 @ h1[t]; gate1 -> h2[t] ----------
        if (mat == 1) {
            u64 accB[6] = {0,0,0,0,0,0};
            const float* hsrc = g_h1T + (size_t)t*HB;
            for (int kc = 0; kc < 4; kc++) {
                __syncthreads();
                const float4* s4 = (const float4*)(hsrc + kc*16384);
                float4* d4 = (float4*)sH;
#pragma unroll
                for (int i2 = 0; i2 < 16; i2++)
                    d4[tid + 256*i2] = __ldcg(s4 + tid + 256*i2);
                __syncthreads();
                chunk3(sWi + rg*512 + kc*128, sH, b0, accB);
            }
            float giR[4], giZ[4], giN[4], ghr[4], ghz[4], ghn[4];
            UNPK6(accB, giR, giZ, giN);
            UNPK6(accA, ghr, ghz, ghn);
            float4 hnew; float* hv = (float*)&hnew;
#pragma unroll
            for (int i = 0; i < 4; i++) {
                float gir = giR[i]+biR, giz = giZ[i]+biZ, gin = giN[i]+biN;
                float R = ghr[i]+bhR, Z = ghz[i]+bhZ, N = ghn[i]+bhN;
                float r = sigm(gir+R), zg = sigm(giz+Z), nvl = tanhf(gin + r*N);
                float h = (1.f - zg)*nvl + zg*hp[i];
                hp[i] = h; hv[i] = h;
            }
            *(float4*)(g_h2T + (size_t)t*HB + (size_t)j*128 + b0) = hnew;
        }
        gridbar(2*t + 2);
    }
}

// ---------------- generic tiled fp32 GEMM (ascending-k chain) --------------
template<int BM, int BN, int BK, int TM, int TN, bool A_ROW, bool B_NK>
__global__ void sgemm_k(const float* __restrict__ Ag, const float* __restrict__ Bg,
                        float* __restrict__ Cg, const float* __restrict__ bias,
                        int K, int lda, int ldb, int ldc,
                        long aZ, long bZ, long cZ)
{
    const float* A = Ag + (long)blockIdx.z * aZ;
    const float* B = Bg + (long)blockIdx.z * bZ;
    float*       C = Cg + (long)blockIdx.z * cZ;
    __shared__ float As[BK][BM];
    __shared__ float Bs[BK][BN];
    constexpr int NTH = (BM / TM) * (BN / TN);
    const int tid  = threadIdx.x;
    const int tcol = tid % (BN / TN);
    const int trow = tid / (BN / TN);
    const int m0   = blockIdx.y * BM;
    const int n0   = blockIdx.x * BN;
    float acc[TM][TN];
#pragma unroll
    for (int i = 0; i < TM; i++)
#pragma unroll
        for (int jx = 0; jx < TN; jx++) acc[i][jx] = 0.f;
    for (int k0 = 0; k0 < K; k0 += BK) {
#pragma unroll
        for (int idx = tid; idx < BM * BK; idx += NTH) {
            int m = idx / BK, kk = idx % BK;
            As[kk][m] = A_ROW ? A[(long)(m0 + m) * lda + (k0 + kk)]
                              : A[(long)(k0 + kk) * lda + (m0 + m)];
        }
#pragma unroll
        for (int idx = tid; idx < BK * BN; idx += NTH) {
            int kk = idx / BN, n = idx % BN;
            Bs[kk][n] = B_NK ? B[(long)(n0 + n) * ldb + (k0 + kk)]
                             : B[(long)(k0 + kk) * ldb + (n0 + n)];
        }
        __syncthreads();
#pragma unroll
        for (int kk = 0; kk < BK; kk++) {
            float a[TM], b[TN];
#pragma unroll
            for (int i = 0; i < TM; i++) a[i] = As[kk][trow * TM + i];
#pragma unroll
            for (int jx = 0; jx < TN; jx++) b[jx] = Bs[kk][tcol * TN + jx];
#pragma unroll
            for (int i = 0; i < TM; i++)
#pragma unroll
                for (int jx = 0; jx < TN; jx++)
                    acc[i][jx] = fmaf(a[i], b[jx], acc[i][jx]);
        }
        __syncthreads();
    }
#pragma unroll
    for (int i = 0; i < TM; i++) {
        int m = m0 + trow * TM + i;
#pragma unroll
        for (int jx = 0; jx < TN; jx++) {
            int n = n0 + tcol * TN + jx;
            float v = acc[i][jx];
            if (bias) v += bias[n];
            C[(long)m * ldc + n] = v;
        }
    }
}

// ---------------- small precompute kernels ---------------------------------
__global__ void precompC_k(const float* __restrict__ pe, const float* __restrict__ emb,
                           const float* __restrict__ W_pre, const float* __restrict__ b_pre)
{
    int t = blockIdx.x, l = threadIdx.x;
    const float* w = W_pre + l * 512;
    float acc = b_pre[l];
    for (int d = 0; d < 256; d++)
        acc += pe[t * 256 + d] * w[d] + emb[t * 256 + d] * w[256 + d];
    g_Cm[t * 256 + l] = acc;
}

__global__ void precompzW_k(const float* __restrict__ z, const float* __restrict__ W_pre)
{
    int b = blockIdx.x, l = threadIdx.x;
    const float* w = W_pre + l * 512;
    float acc = 0.f;
    for (int d = 0; d < 256; d++)
        acc += z[b * 256 + d] * w[d];
    g_zWT[l * BATCH + b] = acc;
}

__global__ void pairidx_k()
{
    int p = blockIdx.x * blockDim.x + threadIdx.x;
    if (p >= NPAIRS) return;
    int i = 0, rem = p;
    while (rem >= 63 - i) { rem -= 63 - i; i++; }
    g_ii[p] = i;
    g_jj[p] = i + 1 + rem;
}

__global__ void zero_k(float* p, int n)
{
    int i = blockIdx.x * blockDim.x + threadIdx.x;
    if (i < n) p[i] = 0.f;
}

// ---------------- pair kernel (unchanged numerics) -------------------------
__global__ void pair_k(const float* __restrict__ W2, const float* __restrict__ b2,
                       const float* __restrict__ gu, const int* __restrict__ n_nodes,
                       float* __restrict__ out)
{
    int b    = blockIdx.x;
    int warp = (int)(blockIdx.y * 8 + (threadIdx.x >> 5));
    int lane = threadIdx.x & 31;
    int nb   = n_nodes[b];
    float* ob = out + (long)b * (MNODES * MNODES);

    float4 w2a[4], w2b[4];
#pragma unroll
    for (int q = 0; q < 4; q++) {
        w2a[q] = *(const float4*)(W2 + 4 * lane + 128 * q);
        w2b[q] = *(const float4*)(W2 + HIDDEN + 4 * lane + 128 * q);
    }
    for (int p = warp; p < NPAIRS; p += 16) {
        int jn = g_jj[p];
        if (jn >= nb) continue;
        int in = g_ii[p];
        const float* Ui = g_U + ((long)b * MNODES + in) * HIDDEN;
        const float* Vj = g_V + ((long)b * MNODES + jn) * HIDDEN;
        float a0 = 0.f, a1 = 0.f;
#pragma unroll
        for (int q = 0; q < 4; q++) {
            float4 u = *(const float4*)(Ui + 4 * lane + 128 * q);
            float4 v = *(const float4*)(Vj + 4 * lane + 128 * q);
            float m;
            m = fmaxf(u.x + v.x, 0.f); a0 = fmaf(m, w2a[q].x, a0); a1 = fmaf(m, w2b[q].x, a1);
            m = fmaxf(u.y + v.y, 0.f); a0 = fmaf(m, w2a[q].y, a0); a1 = fmaf(m, w2b[q].y, a1);
            m = fmaxf(u.z + v.z, 0.f); a0 = fmaf(m, w2a[q].z, a0); a1 = fmaf(m, w2b[q].z, a1);
            m = fmaxf(u.w + v.w, 0.f); a0 = fmaf(m, w2a[q].w, a0); a1 = fmaf(m, w2b[q].w, a1);
        }
#pragma unroll
        for (int s = 16; s > 0; s >>= 1) {
            a0 += __shfl_xor_sync(0xffffffffu, a0, s);
            a1 += __shfl_xor_sync(0xffffffffu, a1, s);
        }
        if (lane == 0) {
            float l0 = a0 + b2[0];
            float l1 = a1 + b2[1];
            const float* g = gu + ((long)b * NPAIRS + p) * 2;
            float g0 = -logf(-logf(g[0] + 1e-10f) + 1e-10f);
            float g1 = -logf(-logf(g[1] + 1e-10f) + 1e-10f);
            if (l0 + g0 >= l1 + g1) {
                ob[in * MNODES + jn] = 1.f;
                ob[jn * MNODES + in] = 1.f;
            }
        }
    }
}

// ---------------- host launch sequence -------------------------------------
extern "C" void kernel_launch(void* const* d_in, const int* in_sizes, int n_in,
                              void* d_out, int out_size)
{
    const float* z       = (const float*)d_in[0];
    const int*   n_nodes = (const int*)  d_in[1];
    const float* gu      = (const float*)d_in[3];
    const float* emb     = (const float*)d_in[4];
    const float* pe      = (const float*)d_in[5];
    const float* W_pre   = (const float*)d_in[6];
    const float* b_pre   = (const float*)d_in[7];
    const float* Wih0    = (const float*)d_in[8];
    const float* Whh0    = (const float*)d_in[9];
    const float* bih0    = (const float*)d_in[10];
    const float* bhh0    = (const float*)d_in[11];
    const float* Wih1    = (const float*)d_in[12];
    const float* Whh1    = (const float*)d_in[13];
    const float* bih1    = (const float*)d_in[14];
    const float* bhh1    = (const float*)d_in[15];
    const float* node_W  = (const float*)d_in[16];
    const float* adj_W1  = (const float*)d_in[17];
    const float* adj_b1  = (const float*)d_in[18];
    const float* adj_W2  = (const float*)d_in[19];
    const float* adj_b2  = (const float*)d_in[20];
    float* out = (float*)d_out;

    float *Cm, *zWT, *AT, *D, *P, *Q, *h2T;
    cudaGetSymbolAddress((void**)&Cm,  g_Cm);
    cudaGetSymbolAddress((void**)&zWT, g_zWT);
    cudaGetSymbolAddress((void**)&AT,  g_AT);
    cudaGetSymbolAddress((void**)&D,   g_D);
    cudaGetSymbolAddress((void**)&P,   g_P);
    cudaGetSymbolAddress((void**)&Q,   g_Q);
    cudaGetSymbolAddress((void**)&h2T, g_h2T);
    float *U, *V;
    cudaGetSymbolAddress((void**)&U, g_U);
    cudaGetSymbolAddress((void**)&V, g_V);

    static int smem_set = 0;
    if (!smem_set) {
        cudaFuncSetAttribute(rnn_fused, cudaFuncAttributeMaxDynamicSharedMemorySize, 163840);
        smem_set = 1;
    }

    // --- precompute ------------------------------------------------------
    pairidx_k<<<8, 256>>>();
    precompC_k<<<MNODES, 256>>>(pe, emb, W_pre, b_pre);
    precompzW_k<<<BATCH, 256>>>(z, W_pre);

    // AT[g][b] = Wih0 @ zW^T : M=1536, N=128, K=256
    sgemm_k<64, 32, 16, 4, 2, true, false><<<dim3(BATCH / 32, G3 / 64), 256>>>(
        Wih0, zWT, AT, nullptr, LATENT, LATENT, BATCH, BATCH, 0, 0, 0);
    // D[t][g] = Cm @ Wih0^T : M=64, N=1536, K=256
    sgemm_k<64, 64, 16, 4, 4, true, true><<<dim3(G3 / 64, 1), 256>>>(
        Cm, Wih0, D, nullptr, LATENT, LATENT, LATENT, G3, 0, 0, 0);
    // P/Q = adj_W1 halves @ node_W : 512x512, K=512
    sgemm_k<64, 64, 16, 4, 4, true, false><<<dim3(8, 8), 256>>>(
        adj_W1, node_W, P, nullptr, HIDDEN, 2 * HIDDEN, HIDDEN, HIDDEN, 0, 0, 0);
    sgemm_k<64, 64, 16, 4, 4, true, false><<<dim3(8, 8), 256>>>(
        adj_W1 + HIDDEN, node_W, Q, nullptr, HIDDEN, 2 * HIDDEN, HIDDEN, HIDDEN, 0, 0, 0);

    // --- fused persistent recurrence -------------------------------------
    reset_bar_k<<<1, 1>>>();
    rnn_fused<<<128, 256, 163840>>>(Whh0, Whh1, Wih1, bih0, bhh0, bih1, bhh1, n_nodes);

    // --- U/V: batched over t (h2T[t] is K-major [k][b]) -------------------
    sgemm_k<64, 64, 16, 4, 4, false, true><<<dim3(HIDDEN / 64, BATCH / 64, MNODES), 256>>>(
        h2T, P, U, nullptr, HIDDEN, BATCH, HIDDEN, MNODES * HIDDEN,
        (long)HB, 0, (long)HIDDEN);
    sgemm_k<64, 64, 16, 4, 4, false, true><<<dim3(HIDDEN / 64, BATCH / 64, MNODES), 256>>>(
        h2T, Q, V, adj_b1, HIDDEN, BATCH, HIDDEN, MNODES * HIDDEN,
        (long)HB, 0, (long)HIDDEN);

    // --- output ----------------------------------------------------------
    zero_k<<<(BATCH * MNODES * MNODES + 255) / 256, 256>>>(out, BATCH * MNODES * MNODES);
    pair_k<<<dim3(BATCH, 2), 256>>>(adj_W2, adj_b2, gu, n_nodes, out);
}

// round 7
// speedup vs baseline: 2.2189x; 1.1077x over previous
#include <cuda_runtime.h>
#include <math.h>

#define BATCH  128
#define LATENT 256
#define HIDDEN 512
#define MNODES 64
#define NPAIRS 2016
#define G3     1536
#define HB     65536

typedef unsigned long long u64;

// ---------------- device scratch -------------------------------------------
__device__ __align__(16) float g_Cm [MNODES*LATENT];
__device__ __align__(16) float g_zWT[LATENT*BATCH];
__device__ __align__(16) float g_AT [G3*BATCH];        // [g][b]
__device__ __align__(16) float g_D  [MNODES*G3];       // [t][g]
__device__ __align__(16) float g_P  [HIDDEN*HIDDEN];
__device__ __align__(16) float g_Q  [HIDDEN*HIDDEN];
__device__ __align__(16) float g_gh [G3*BATCH];        // gh1 staging [g][b]
__device__ __align__(16) float g_h1T[MNODES*HB];       // [t][k][b]
__device__ __align__(16) float g_h2T[MNODES*HB];       // [t][k][b]
__device__ __align__(16) float g_U  [BATCH*MNODES*HIDDEN];
__device__ __align__(16) float g_V  [BATCH*MNODES*HIDDEN];
__device__ int g_ii[NPAIRS];
__device__ int g_jj[NPAIRS];
__device__ unsigned g_bar_cnt;
__device__ unsigned g_bar_gen;

// ---------------- f32x2 helpers (lanes = independent IEEE fma chains) ------
__device__ __forceinline__ u64 pack2(float x){u64 r;asm("mov.b64 %0,{%1,%1};":"=l"(r):"f"(x));return r;}
__device__ __forceinline__ void fma2(u64&a,u64 b,u64 c){asm("fma.rn.f32x2 %0, %1, %2, %0;":"+l"(a):"l"(b),"l"(c));}
__device__ __forceinline__ float2 unpk(u64 v){float2 f;asm("mov.b64 {%0,%1},%2;":"=f"(f.x),"=f"(f.y):"l"(v));return f;}
__device__ __forceinline__ float sigm(float x){return 1.f/(1.f+expf(-x));}

__global__ void reset_bar_k(){ g_bar_cnt = 0u; g_bar_gen = 0u; }

__device__ __forceinline__ void gridbar(int call)
{
    __syncthreads();
    if (threadIdx.x == 0) {
        __threadfence();
        unsigned prev = atomicAdd(&g_bar_cnt, 1u);
        if (prev == (unsigned)(call * 128 - 1)) {
            atomicExch(&g_bar_gen, (unsigned)call);
        } else {
            while (*(volatile unsigned*)&g_bar_gen < (unsigned)call) {}
        }
        __threadfence();
    }
    __syncthreads();
}

// ---------------- staging: 128k x 128b chunk (64KB) via L2 -----------------
__device__ __forceinline__ void stageH(float* sH, const float* src, int tid)
{
    const float4* s4 = (const float4*)src;
    float4* d4 = (float4*)sH;
#pragma unroll
    for (int i = 0; i < 16; i++)
        d4[tid + 256*i] = __ldcg(s4 + tid + 256*i);
}

// ---------------- accumulators ---------------------------------------------
// A: 2 rows x 3 gates x 2 b.  h: coalesced LDS.64 at b0=2*bq.
__device__ __forceinline__ void accA6(const float* const (&wp)[2][3], const float* sH,
                                      int b0, int kbase, u64 (&acc)[2][3])
{
#pragma unroll 2
    for (int k = 0; k < 128; k += 4) {
        float4 wv[2][3];
#pragma unroll
        for (int r = 0; r < 2; r++)
#pragma unroll
            for (int g = 0; g < 3; g++)
                wv[r][g] = *(const float4*)(wp[r][g] + kbase + k);
        u64 h[4];
#pragma unroll
        for (int q = 0; q < 4; q++)
            h[q] = *(const u64*)(sH + (k + q)*128 + b0);
#pragma unroll
        for (int q = 0; q < 4; q++)
#pragma unroll
            for (int r = 0; r < 2; r++)
#pragma unroll
                for (int g = 0; g < 3; g++)
                    fma2(acc[r][g], pack2(((const float*)&wv[r][g])[q]), h[q]);
    }
}

// B: 1 row x 3 gates x 2 b.
__device__ __forceinline__ void accB3(const float* const (&wq)[3], const float* sH,
                                      int b0, int kbase, u64 (&acc)[3])
{
#pragma unroll 2
    for (int k = 0; k < 128; k += 4) {
        float4 wv[3];
#pragma unroll
        for (int g = 0; g < 3; g++)
            wv[g] = *(const float4*)(wq[g] + kbase + k);
        u64 h[4];
#pragma unroll
        for (int q = 0; q < 4; q++)
            h[q] = *(const u64*)(sH + (k + q)*128 + b0);
#pragma unroll
        for (int q = 0; q < 4; q++)
#pragma unroll
            for (int g = 0; g < 3; g++)
                fma2(acc[g], pack2(((const float*)&wv[g])[q]), h[q]);
    }
}

// ---------------- persistent fused 2-layer GRU -----------------------------
// 128 CTAs x 256 thr. Phase A: mat=bx&1, 8 j rows/CTA (thread: 2 rows x 2 b).
// Phase B (all CTAs): 4 j rows/CTA, thread: 1 row x 3 gates x 2 b.
// Smem: sW 48KB (recurrent rows), sWi 24KB (Wih1 rows), sH 64KB (h chunk).
__global__ void __launch_bounds__(256, 1)
rnn_fused(const float* __restrict__ Whh0, const float* __restrict__ Whh1,
          const float* __restrict__ Wih1,
          const float* __restrict__ bih0, const float* __restrict__ bhh0,
          const float* __restrict__ bih1, const float* __restrict__ bhh1,
          const int* __restrict__ n_nodes)
{
    extern __shared__ float sm[];
    float* sW  = sm;            // 12288 floats
    float* sWi = sm + 12288;    // 6144 floats
    float* sH  = sm + 18432;    // 16384 floats

    const int tid  = threadIdx.x;
    const int bx   = blockIdx.x;
    const int mat  = bx & 1;
    const int j0   = (bx >> 1) * 8;
    const int bq   = tid & 63;
    const int rgrp = tid >> 6;          // 0..3
    const int b0   = bq * 2;
    const int jj0  = rgrp * 2;

    // ---- stage weights (once) ----
    const float* Wrec = mat ? Whh1 : Whh0;
    for (int i = tid; i < 3072; i += 256) {           // sW: 24 rows x 128 f4
        int r = i >> 7, c = i & 127;
        ((float4*)sW)[i] = *(const float4*)(Wrec + (size_t)((r>>3)*512 + j0 + (r&7))*512 + c*4);
    }
    for (int i = tid; i < 1536; i += 256) {           // sWi: 12 rows x 128 f4
        int r = i >> 7, c = i & 127;
        ((float4*)sWi)[i] = *(const float4*)(Wih1 + (size_t)((r>>2)*512 + bx*4 + (r&3))*512 + c*4);
    }
    __syncthreads();

    // ---- per-thread constants ----
    const float* wp[2][3];
#pragma unroll
    for (int r = 0; r < 2; r++)
#pragma unroll
        for (int g = 0; g < 3; g++)
            wp[r][g] = sW + (size_t)(g*8 + jj0 + r)*512;

    const int jb = bx*4 + rgrp;          // phase-B row
    const float* wq[3];
#pragma unroll
    for (int g = 0; g < 3; g++)
        wq[g] = sWi + (size_t)(g*4 + rgrp)*512;

    float biR[2], biZ[2], biN[2], bhR[2], bhZ[2], bhN[2];
    float2 atr[2], atz[2], atn[2];
    int2 nni = make_int2(0, 0);
    if (mat == 0) {
        nni = *(const int2*)(n_nodes + b0);
#pragma unroll
        for (int r = 0; r < 2; r++) {
            int j = j0 + jj0 + r;
            biR[r]=bih0[j]; biZ[r]=bih0[512+j]; biN[r]=bih0[1024+j];
            bhR[r]=bhh0[j]; bhZ[r]=bhh0[512+j]; bhN[r]=bhh0[1024+j];
            atr[r] = *(const float2*)(g_AT + (size_t)j*128 + b0);
            atz[r] = *(const float2*)(g_AT + (size_t)(512+j)*128 + b0);
            atn[r] = *(const float2*)(g_AT + (size_t)(1024+j)*128 + b0);
        }
    }
    const float bi1R = bih1[jb], bi1Z = bih1[512+jb], bi1N = bih1[1024+jb];
    const float bh1R = bhh1[jb], bh1Z = bhh1[512+jb], bh1N = bhh1[1024+jb];

    float hp[4] = {0.f, 0.f, 0.f, 0.f};   // layer-0 hidden regs (mat0)

    for (int t = 0; t < MNODES; t++) {
        // ============ phase A: gh0 (mat0) / gh1 (mat1) ====================
        u64 acc[2][3] = {{0,0,0},{0,0,0}};
        if (t > 0) {
            const float* hsrc = (mat ? g_h2T : g_h1T) + (size_t)(t-1)*HB;
            for (int kc = 0; kc < 4; kc++) {
                __syncthreads();
                stageH(sH, hsrc + kc*16384, tid);
                __syncthreads();
                accA6(wp, sH, b0, kc*128, acc);
            }
        }

        if (mat == 0) {   // gate0 -> h1[t]
#pragma unroll
            for (int r = 0; r < 2; r++) {
                int j = j0 + jj0 + r;
                float2 vR = unpk(acc[r][0]), vZ = unpk(acc[r][1]), vN = unpk(acc[r][2]);
                float dR = __ldg(g_D + (size_t)t*G3 + j);
                float dZ = __ldg(g_D + (size_t)t*G3 + 512 + j);
                float dN = __ldg(g_D + (size_t)t*G3 + 1024 + j);
                float hr[2]={vR.x,vR.y}, hz[2]={vZ.x,vZ.y}, hn[2]={vN.x,vN.y};
                float ar[2]={atr[r].x,atr[r].y}, az[2]={atz[r].x,atz[r].y}, an[2]={atn[r].x,atn[r].y};
                int nv[2]={nni.x,nni.y};
                float out[2];
#pragma unroll
                for (int i = 0; i < 2; i++) {
                    float gir=biR[r], giz=biZ[r], gin=biN[r];
                    if (t < nv[i]) { gir += ar[i]+dR; giz += az[i]+dZ; gin += an[i]+dN; }
                    float R=hr[i]+bhR[r], Z=hz[i]+bhZ[r], N=hn[i]+bhN[r];
                    float rr=sigm(gir+R), zz=sigm(giz+Z), nl=tanhf(gin+rr*N);
                    float h=(1.f-zz)*nl+zz*hp[r*2+i];
                    hp[r*2+i]=h; out[i]=h;
                }
                *(float2*)(g_h1T + (size_t)t*HB + (size_t)j*128 + b0) = make_float2(out[0],out[1]);
            }
        } else {          // store gh1 for phase B
#pragma unroll
            for (int r = 0; r < 2; r++) {
                int j = j0 + jj0 + r;
#pragma unroll
                for (int g = 0; g < 3; g++)
                    *(u64*)(g_gh + (size_t)(g*512+j)*128 + b0) = acc[r][g];
            }
        }
        gridbar(2*t + 1);

        // ============ phase B: gi1 + gate1 -> h2[t] (all CTAs) ============
        {
            u64 accB[3] = {0,0,0};
            const float* hsrc = g_h1T + (size_t)t*HB;
            for (int kc = 0; kc < 4; kc++) {
                __syncthreads();
                stageH(sH, hsrc + kc*16384, tid);
                __syncthreads();
                accB3(wq, sH, b0, kc*128, accB);
            }
            float2 giR = unpk(accB[0]), giZ = unpk(accB[1]), giN = unpk(accB[2]);
            float2 ghR = __ldcg((const float2*)(g_gh + (size_t)jb*128 + b0));
            float2 ghZ = __ldcg((const float2*)(g_gh + (size_t)(512+jb)*128 + b0));
            float2 ghN = __ldcg((const float2*)(g_gh + (size_t)(1024+jb)*128 + b0));
            float2 h2p = make_float2(0.f, 0.f);
            if (t > 0)
                h2p = __ldcg((const float2*)(g_h2T + (size_t)(t-1)*HB + (size_t)jb*128 + b0));
            float gia[2]={giR.x,giR.y}, gza[2]={giZ.x,giZ.y}, gna[2]={giN.x,giN.y};
            float ra[2]={ghR.x,ghR.y}, za[2]={ghZ.x,ghZ.y}, na[2]={ghN.x,ghN.y};
            float hpv[2]={h2p.x,h2p.y}, out[2];
#pragma unroll
            for (int i = 0; i < 2; i++) {
                float gir=gia[i]+bi1R, giz=gza[i]+bi1Z, gin=gna[i]+bi1N;
                float R=ra[i]+bh1R, Z=za[i]+bh1Z, N=na[i]+bh1N;
                float rr=sigm(gir+R), zz=sigm(giz+Z), nl=tanhf(gin+rr*N);
                out[i]=(1.f-zz)*nl+zz*hpv[i];
            }
            *(float2*)(g_h2T + (size_t)t*HB + (size_t)jb*128 + b0) = make_float2(out[0],out[1]);
        }
        gridbar(2*t + 2);
    }
}

// ---------------- generic tiled fp32 GEMM (ascending-k chain) --------------
template<int BM, int BN, int BK, int TM, int TN, bool A_ROW, bool B_NK>
__global__ void sgemm_k(const float* __restrict__ Ag, const float* __restrict__ Bg,
                        float* __restrict__ Cg, const float* __restrict__ bias,
                        int K, int lda, int ldb, int ldc,
                        long aZ, long bZ, long cZ)
{
    const float* A = Ag + (long)blockIdx.z * aZ;
    const float* B = Bg + (long)blockIdx.z * bZ;
    float*       C = Cg + (long)blockIdx.z * cZ;
    __shared__ float As[BK][BM];
    __shared__ float Bs[BK][BN];
    constexpr int NTH = (BM / TM) * (BN / TN);
    const int tid  = threadIdx.x;
    const int tcol = tid % (BN / TN);
    const int trow = tid / (BN / TN);
    const int m0   = blockIdx.y * BM;
    const int n0   = blockIdx.x * BN;
    float acc[TM][TN];
#pragma unroll
    for (int i = 0; i < TM; i++)
#pragma unroll
        for (int jx = 0; jx < TN; jx++) acc[i][jx] = 0.f;
    for (int k0 = 0; k0 < K; k0 += BK) {
#pragma unroll
        for (int idx = tid; idx < BM * BK; idx += NTH) {
            int m = idx / BK, kk = idx % BK;
            As[kk][m] = A_ROW ? A[(long)(m0 + m) * lda + (k0 + kk)]
                              : A[(long)(k0 + kk) * lda + (m0 + m)];
        }
#pragma unroll
        for (int idx = tid; idx < BK * BN; idx += NTH) {
            int kk = idx / BN, n = idx % BN;
            Bs[kk][n] = B_NK ? B[(long)(n0 + n) * ldb + (k0 + kk)]
                             : B[(long)(k0 + kk) * ldb + (n0 + n)];
        }
        __syncthreads();
#pragma unroll
        for (int kk = 0; kk < BK; kk++) {
            float a[TM], b[TN];
#pragma unroll
            for (int i = 0; i < TM; i++) a[i] = As[kk][trow * TM + i];
#pragma unroll
            for (int jx = 0; jx < TN; jx++) b[jx] = Bs[kk][tcol * TN + jx];
#pragma unroll
            for (int i = 0; i < TM; i++)
#pragma unroll
                for (int jx = 0; jx < TN; jx++)
                    acc[i][jx] = fmaf(a[i], b[jx], acc[i][jx]);
        }
        __syncthreads();
    }
#pragma unroll
    for (int i = 0; i < TM; i++) {
        int m = m0 + trow * TM + i;
#pragma unroll
        for (int jx = 0; jx < TN; jx++) {
            int n = n0 + tcol * TN + jx;
            float v = acc[i][jx];
            if (bias) v += bias[n];
            C[(long)m * ldc + n] = v;
        }
    }
}

// ---------------- small precompute kernels ---------------------------------
__global__ void precompC_k(const float* __restrict__ pe, const float* __restrict__ emb,
                           const float* __restrict__ W_pre, const float* __restrict__ b_pre)
{
    int t = blockIdx.x, l = threadIdx.x;
    const float* w = W_pre + l * 512;
    float acc = b_pre[l];
    for (int d = 0; d < 256; d++)
        acc += pe[t * 256 + d] * w[d] + emb[t * 256 + d] * w[256 + d];
    g_Cm[t * 256 + l] = acc;
}

__global__ void precompzW_k(const float* __restrict__ z, const float* __restrict__ W_pre)
{
    int b = blockIdx.x, l = threadIdx.x;
    const float* w = W_pre + l * 512;
    float acc = 0.f;
    for (int d = 0; d < 256; d++)
        acc += z[b * 256 + d] * w[d];
    g_zWT[l * BATCH + b] = acc;
}

__global__ void pairidx_k()
{
    int p = blockIdx.x * blockDim.x + threadIdx.x;
    if (p >= NPAIRS) return;
    int i = 0, rem = p;
    while (rem >= 63 - i) { rem -= 63 - i; i++; }
    g_ii[p] = i;
    g_jj[p] = i + 1 + rem;
}

__global__ void zero_k(float* p, int n)
{
    int i = blockIdx.x * blockDim.x + threadIdx.x;
    if (i < n) p[i] = 0.f;
}

// ---------------- pair kernel (unchanged numerics) -------------------------
__global__ void pair_k(const float* __restrict__ W2, const float* __restrict__ b2,
                       const float* __restrict__ gu, const int* __restrict__ n_nodes,
                       float* __restrict__ out)
{
    int b    = blockIdx.x;
    int warp = (int)(blockIdx.y * 8 + (threadIdx.x >> 5));
    int lane = threadIdx.x & 31;
    int nb   = n_nodes[b];
    float* ob = out + (long)b * (MNODES * MNODES);

    float4 w2a[4], w2b[4];
#pragma unroll
    for (int q = 0; q < 4; q++) {
        w2a[q] = *(const float4*)(W2 + 4 * lane + 128 * q);
        w2b[q] = *(const float4*)(W2 + HIDDEN + 4 * lane + 128 * q);
    }
    for (int p = warp; p < NPAIRS; p += 16) {
        int jn = g_jj[p];
        if (jn >= nb) continue;
        int in = g_ii[p];
        const float* Ui = g_U + ((long)b * MNODES + in) * HIDDEN;
        const float* Vj = g_V + ((long)b * MNODES + jn) * HIDDEN;
        float a0 = 0.f, a1 = 0.f;
#pragma unroll
        for (int q = 0; q < 4; q++) {
            float4 u = *(const float4*)(Ui + 4 * lane + 128 * q);
            float4 v = *(const float4*)(Vj + 4 * lane + 128 * q);
            float m;
            m = fmaxf(u.x + v.x, 0.f); a0 = fmaf(m, w2a[q].x, a0); a1 = fmaf(m, w2b[q].x, a1);
            m = fmaxf(u.y + v.y, 0.f); a0 = fmaf(m, w2a[q].y, a0); a1 = fmaf(m, w2b[q].y, a1);
            m = fmaxf(u.z + v.z, 0.f); a0 = fmaf(m, w2a[q].z, a0); a1 = fmaf(m, w2b[q].z, a1);
            m = fmaxf(u.w + v.w, 0.f); a0 = fmaf(m, w2a[q].w, a0); a1 = fmaf(m, w2b[q].w, a1);
        }
#pragma unroll
        for (int s = 16; s > 0; s >>= 1) {
            a0 += __shfl_xor_sync(0xffffffffu, a0, s);
            a1 += __shfl_xor_sync(0xffffffffu, a1, s);
        }
        if (lane == 0) {
            float l0 = a0 + b2[0];
            float l1 = a1 + b2[1];
            const float* g = gu + ((long)b * NPAIRS + p) * 2;
            float g0 = -logf(-logf(g[0] + 1e-10f) + 1e-10f);
            float g1 = -logf(-logf(g[1] + 1e-10f) + 1e-10f);
            if (l0 + g0 >= l1 + g1) {
                ob[in * MNODES + jn] = 1.f;
                ob[jn * MNODES + in] = 1.f;
            }
        }
    }
}

// ---------------- host launch sequence -------------------------------------
extern "C" void kernel_launch(void* const* d_in, const int* in_sizes, int n_in,
                              void* d_out, int out_size)
{
    const float* z       = (const float*)d_in[0];
    const int*   n_nodes = (const int*)  d_in[1];
    const float* gu      = (const float*)d_in[3];
    const float* emb     = (const float*)d_in[4];
    const float* pe      = (const float*)d_in[5];
    const float* W_pre   = (const float*)d_in[6];
    const float* b_pre   = (const float*)d_in[7];
    const float* Wih0    = (const float*)d_in[8];
    const float* Whh0    = (const float*)d_in[9];
    const float* bih0    = (const float*)d_in[10];
    const float* bhh0    = (const float*)d_in[11];
    const float* Wih1    = (const float*)d_in[12];
    const float* Whh1    = (const float*)d_in[13];
    const float* bih1    = (const float*)d_in[14];
    const float* bhh1    = (const float*)d_in[15];
    const float* node_W  = (const float*)d_in[16];
    const float* adj_W1  = (const float*)d_in[17];
    const float* adj_b1  = (const float*)d_in[18];
    const float* adj_W2  = (const float*)d_in[19];
    const float* adj_b2  = (const float*)d_in[20];
    float* out = (float*)d_out;

    float *Cm, *zWT, *AT, *D, *P, *Q, *h2T, *U, *V;
    cudaGetSymbolAddress((void**)&Cm,  g_Cm);
    cudaGetSymbolAddress((void**)&zWT, g_zWT);
    cudaGetSymbolAddress((void**)&AT,  g_AT);
    cudaGetSymbolAddress((void**)&D,   g_D);
    cudaGetSymbolAddress((void**)&P,   g_P);
    cudaGetSymbolAddress((void**)&Q,   g_Q);
    cudaGetSymbolAddress((void**)&h2T, g_h2T);
    cudaGetSymbolAddress((void**)&U,   g_U);
    cudaGetSymbolAddress((void**)&V,   g_V);

    static int smem_set = 0;
    if (!smem_set) {
        cudaFuncSetAttribute(rnn_fused, cudaFuncAttributeMaxDynamicSharedMemorySize, 139264);
        smem_set = 1;
    }

    // --- precompute ------------------------------------------------------
    pairidx_k<<<8, 256>>>();
    precompC_k<<<MNODES, 256>>>(pe, emb, W_pre, b_pre);
    precompzW_k<<<BATCH, 256>>>(z, W_pre);

    sgemm_k<64, 32, 16, 4, 2, true, false><<<dim3(BATCH / 32, G3 / 64), 256>>>(
        Wih0, zWT, AT, nullptr, LATENT, LATENT, BATCH, BATCH, 0, 0, 0);
    sgemm_k<64, 64, 16, 4, 4, true, true><<<dim3(G3 / 64, 1), 256>>>(
        Cm, Wih0, D, nullptr, LATENT, LATENT, LATENT, G3, 0, 0, 0);
    sgemm_k<64, 64, 16, 4, 4, true, false><<<dim3(8, 8), 256>>>(
        adj_W1, node_W, P, nullptr, HIDDEN, 2 * HIDDEN, HIDDEN, HIDDEN, 0, 0, 0);
    sgemm_k<64, 64, 16, 4, 4, true, false><<<dim3(8, 8), 256>>>(
        adj_W1 + HIDDEN, node_W, Q, nullptr, HIDDEN, 2 * HIDDEN, HIDDEN, HIDDEN, 0, 0, 0);

    // --- fused persistent recurrence -------------------------------------
    reset_bar_k<<<1, 1>>>();
    rnn_fused<<<128, 256, 139264>>>(Whh0, Whh1, Wih1, bih0, bhh0, bih1, bhh1, n_nodes);

    // --- U/V --------------------------------------------------------------
    sgemm_k<64, 64, 16, 4, 4, false, true><<<dim3(HIDDEN / 64, BATCH / 64, MNODES), 256>>>(
        h2T, P, U, nullptr, HIDDEN, BATCH, HIDDEN, MNODES * HIDDEN,
        (long)HB, 0, (long)HIDDEN);
    sgemm_k<64, 64, 16, 4, 4, false, true><<<dim3(HIDDEN / 64, BATCH / 64, MNODES), 256>>>(
        h2T, Q, V, adj_b1, HIDDEN, BATCH, HIDDEN, MNODES * HIDDEN,
        (long)HB, 0, (long)HIDDEN);

    // --- output ----------------------------------------------------------
    zero_k<<<(BATCH * MNODES * MNODES + 255) / 256, 256>>>(out, BATCH * MNODES * MNODES);
    pair_k<<<dim3(BATCH, 2), 256>>>(adj_W2, adj_b2, gu, n_nodes, out);
}

// round 9
// speedup vs baseline: 2.2408x; 1.0099x over previous
#include <cuda_runtime.h>
#include <math.h>

#define BATCH  128
#define LATENT 256
#define HIDDEN 512
#define MNODES 64
#define NPAIRS 2016
#define G3     1536
#define HB     65536

typedef unsigned long long u64;

// ---------------- device scratch (zero-initialized at load) ----------------
__device__ __align__(16) float g_Cm [MNODES*LATENT];
__device__ __align__(16) float g_zWT[LATENT*BATCH];
__device__ __align__(16) float g_AT [G3*BATCH];        // [g][b]
__device__ __align__(16) float g_D  [MNODES*G3];       // [t][g]
__device__ __align__(16) float g_P  [HIDDEN*HIDDEN];
__device__ __align__(16) float g_Q  [HIDDEN*HIDDEN];
__device__ __align__(16) float g_h1T[MNODES*HB];       // [t][k][b]
__device__ __align__(16) float g_h2T[MNODES*HB];       // [t][k][b]
__device__ __align__(16) float g_zH [HB];              // stays all-zero
__device__ __align__(16) float g_U  [BATCH*MNODES*HIDDEN];
__device__ __align__(16) float g_V  [BATCH*MNODES*HIDDEN];
__device__ int g_ii[NPAIRS];
__device__ int g_jj[NPAIRS];
__device__ unsigned g_bar_cnt;
__device__ unsigned g_bar_gen;

// ---------------- f32x2 helpers (lanes = independent IEEE fma chains) ------
__device__ __forceinline__ u64 pack2(float x){u64 r;asm("mov.b64 %0,{%1,%1};":"=l"(r):"f"(x));return r;}
__device__ __forceinline__ u64 packab(float a,float b){u64 r;asm("mov.b64 %0,{%1,%2};":"=l"(r):"f"(a),"f"(b));return r;}
__device__ __forceinline__ void fma2(u64&a,u64 b,u64 c){asm("fma.rn.f32x2 %0, %1, %2, %0;":"+l"(a):"l"(b),"l"(c));}
__device__ __forceinline__ float2 unpk(u64 v){float2 f;asm("mov.b64 {%0,%1},%2;":"=f"(f.x),"=f"(f.y):"l"(v));return f;}
__device__ __forceinline__ float sigm(float x){return 1.f/(1.f+expf(-x));}

__global__ void reset_bar_k(){ g_bar_cnt = 0u; g_bar_gen = 0u; }

__device__ __forceinline__ void gridbar(int call)
{
    __threadfence();
    __syncthreads();
    if (threadIdx.x == 0) {
        unsigned prev = atomicAdd(&g_bar_cnt, 1u);
        if (prev == (unsigned)(call * 128 - 1)) {
            atomicExch(&g_bar_gen, (unsigned)call);
        } else {
            while (*(volatile unsigned*)&g_bar_gen < (unsigned)call) {}
        }
        __threadfence();
    }
    __syncthreads();
}

// ---------------- cp.async (L2-only .cg form — cross-SM coherent) ----------
__device__ __forceinline__ void cp16(void* smem, const void* gmem){
    unsigned s = (unsigned)__cvta_generic_to_shared(smem);
    asm volatile("cp.async.cg.shared.global [%0], [%1], 16;" :: "r"(s), "l"(gmem) : "memory");
}
__device__ __forceinline__ void cp_commit(){ asm volatile("cp.async.commit_group;" ::: "memory"); }
__device__ __forceinline__ void cp_wait1(){ asm volatile("cp.async.wait_group 1;" ::: "memory"); }
__device__ __forceinline__ void cp_wait0(){ asm volatile("cp.async.wait_group 0;" ::: "memory"); }

// stage one 64k x 128b chunk of h1 and h2 (32KB each) into buf
__device__ __forceinline__ void prefetch(float* buf, const float* h1c, const float* h2c, int tid)
{
#pragma unroll
    for (int i = 0; i < 8; i++)
        cp16(buf + (tid + i*256)*4, h1c + (tid + i*256)*4);
#pragma unroll
    for (int i = 0; i < 8; i++)
        cp16(buf + 8192 + (tid + i*256)*4, h2c + (tid + i*256)*4);
    cp_commit();
}

// 64-k chunk accumulate: 9 outputs (3 mats x 3 gates), lanes = 2 j-rows.
// mats 0..1 (gh0, gi1) read h1 chunk; mat 2 (gh1) reads h2 chunk.
__device__ __forceinline__ void compute64(const float* buf, const u64* w2p, int kbase,
                                          int b, u64 (&acc)[9])
{
    const float* sh1 = buf;
    const float* sh2 = buf + 8192;
#pragma unroll 8
    for (int kk = 0; kk < 64; kk += 2) {
        ulonglong2 wv[9];
#pragma unroll
        for (int mg = 0; mg < 9; mg++)
            wv[mg] = *(const ulonglong2*)(w2p + mg*1024 + kbase + kk);
        u64 p1a = pack2(sh1[kk*128 + b]);
        u64 p1b = pack2(sh1[(kk+1)*128 + b]);
        u64 p2a = pack2(sh2[kk*128 + b]);
        u64 p2b = pack2(sh2[(kk+1)*128 + b]);
#pragma unroll
        for (int mg = 0; mg < 6; mg++) { fma2(acc[mg], wv[mg].x, p1a); fma2(acc[mg], wv[mg].y, p1b); }
#pragma unroll
        for (int mg = 6; mg < 9; mg++) { fma2(acc[mg], wv[mg].x, p2a); fma2(acc[mg], wv[mg].y, p2b); }
    }
}

// ---------------- persistent pipelined 2-layer GRU -------------------------
// 128 CTAs x 256 thr. CTA owns j rows bx*4..bx*4+3 for ALL three GEMMs.
// Super-step s: layer0 t=s (if s<64) and layer1 t=s-1 (if s>=1). ONE barrier.
// Smem: w2 pairs 72KB + 2 x 64KB h double-buffer = 200KB.
__global__ void __launch_bounds__(256, 1)
rnn_pipe(const float* __restrict__ Whh0, const float* __restrict__ Whh1,
         const float* __restrict__ Wih1,
         const float* __restrict__ bih0, const float* __restrict__ bhh0,
         const float* __restrict__ bih1, const float* __restrict__ bhh1,
         const int* __restrict__ n_nodes)
{
    extern __shared__ float sm[];
    u64*   sw2  = (u64*)sm;              // 9216 u64 = 72KB
    float* bufA = sm + 18432;            // 16384 floats
    float* bufB = bufA + 16384;

    const int tid = threadIdx.x;
    const int bx  = blockIdx.x;
    const int p   = tid >> 7;            // j-pair 0/1
    const int b   = tid & 127;
    const int jA  = bx*4 + 2*p;

    // stage packed weight pairs: row = (m*3+g)*2 + pr, lanes {j even, j odd}
    for (int i = tid; i < 9216; i += 256) {
        int row = i >> 9, k = i & 511;
        int mg = row >> 1, pr = row & 1;
        int m = mg / 3, g = mg % 3;
        const float* W = (m == 0) ? Whh0 : (m == 1) ? Wih1 : Whh1;
        size_t r0 = (size_t)(g*512 + bx*4 + 2*pr) * 512 + k;
        sw2[i] = packab(W[r0], W[r0 + 512]);
    }
    __syncthreads();
    const u64* w2p = sw2 + p*512;

    // per-thread constants
    float bi0[2][3], bh0[2][3], bi1[2][3], bh1[2][3], at[2][3];
#pragma unroll
    for (int l = 0; l < 2; l++) {
        int j = jA + l;
#pragma unroll
        for (int g = 0; g < 3; g++) {
            bi0[l][g] = bih0[g*512 + j]; bh0[l][g] = bhh0[g*512 + j];
            bi1[l][g] = bih1[g*512 + j]; bh1[l][g] = bhh1[g*512 + j];
            at[l][g]  = g_AT[(size_t)(g*512 + j)*128 + b];
        }
    }
    const int nn = n_nodes[b];
    float h1p[2] = {0.f, 0.f}, h2p[2] = {0.f, 0.f};

    for (int s = 0; s <= 64; s++) {
        const float* b1 = (s >= 1) ? g_h1T + (size_t)(s-1)*HB : g_zH;
        const float* b2 = (s >= 2) ? g_h2T + (size_t)(s-2)*HB : g_zH;
        u64 acc[9] = {0,0,0,0,0,0,0,0,0};

        prefetch(bufA, b1, b2, tid);
        prefetch(bufB, b1 + 8192, b2 + 8192, tid);
        for (int c = 0; c < 8; c++) {
            if (c < 7) cp_wait1(); else cp_wait0();
            __syncthreads();
            float* buf = (c & 1) ? bufB : bufA;
            compute64(buf, w2p, c*64, b, acc);
            __syncthreads();
            if (c < 6) prefetch(buf, b1 + (c+2)*8192, b2 + (c+2)*8192, tid);
        }

        if (s < 64) {   // gate0, t = s
            int t = s;
            float2 vR = unpk(acc[0]), vZ = unpk(acc[1]), vN = unpk(acc[2]);
            float ghr[2]={vR.x,vR.y}, ghz[2]={vZ.x,vZ.y}, ghn[2]={vN.x,vN.y};
#pragma unroll
            for (int l = 0; l < 2; l++) {
                int j = jA + l;
                float dR = __ldg(g_D + (size_t)t*G3 + j);
                float dZ = __ldg(g_D + (size_t)t*G3 + 512 + j);
                float dN = __ldg(g_D + (size_t)t*G3 + 1024 + j);
                float gir = bi0[l][0], giz = bi0[l][1], gin = bi0[l][2];
                if (t < nn) { gir += at[l][0]+dR; giz += at[l][1]+dZ; gin += at[l][2]+dN; }
                float R = ghr[l]+bh0[l][0], Z = ghz[l]+bh0[l][1], N = ghn[l]+bh0[l][2];
                float rr = sigm(gir+R), zz = sigm(giz+Z), nl = tanhf(gin + rr*N);
                float h = (1.f - zz)*nl + zz*h1p[l];
                h1p[l] = h;
                g_h1T[(size_t)s*HB + (size_t)j*128 + b] = h;
            }
        }
        if (s >= 1) {   // gate1, t = s-1
            float2 iR = unpk(acc[3]), iZ = unpk(acc[4]), iN = unpk(acc[5]);
            float2 hR = unpk(acc[6]), hZ = unpk(acc[7]), hN = unpk(acc[8]);
            float gi_[2][3] = {{iR.x,iZ.x,iN.x},{iR.y,iZ.y,iN.y}};
            float gh_[2][3] = {{hR.x,hZ.x,hN.x},{hR.y,hZ.y,hN.y}};
#pragma unroll
            for (int l = 0; l < 2; l++) {
                int j = jA + l;
                float gir = gi_[l][0]+bi1[l][0], giz = gi_[l][1]+bi1[l][1], gin = gi_[l][2]+bi1[l][2];
                float R = gh_[l][0]+bh1[l][0], Z = gh_[l][1]+bh1[l][1], N = gh_[l][2]+bh1[l][2];
                float rr = sigm(gir+R), zz = sigm(giz+Z), nl = tanhf(gin + rr*N);
                float h = (1.f - zz)*nl + zz*h2p[l];
                h2p[l] = h;
                g_h2T[(size_t)(s-1)*HB + (size_t)j*128 + b] = h;
            }
        }
        gridbar(s + 1);
    }
}

// ---------------- generic tiled fp32 GEMM (ascending-k chain) --------------
template<int BM, int BN, int BK, int TM, int TN, bool A_ROW, bool B_NK>
__global__ void sgemm_k(const float* __restrict__ Ag, const float* __restrict__ Bg,
                        float* __restrict__ Cg, const float* __restrict__ bias,
                        int K, int lda, int ldb, int ldc,
                        long aZ, long bZ, long cZ)
{
    const float* A = Ag + (long)blockIdx.z * aZ;
    const float* B = Bg + (long)blockIdx.z * bZ;
    float*       C = Cg + (long)blockIdx.z * cZ;
    __shared__ float As[BK][BM];
    __shared__ float Bs[BK][BN];
    constexpr int NTH = (BM / TM) * (BN / TN);
    const int tid  = threadIdx.x;
    const int tcol = tid % (BN / TN);
    const int trow = tid / (BN / TN);
    const int m0   = blockIdx.y * BM;
    const int n0   = blockIdx.x * BN;
    float acc[TM][TN];
#pragma unroll
    for (int i = 0; i < TM; i++)
#pragma unroll
        for (int jx = 0; jx < TN; jx++) acc[i][jx] = 0.f;
    for (int k0 = 0; k0 < K; k0 += BK) {
#pragma unroll
        for (int idx = tid; idx < BM * BK; idx += NTH) {
            int m = idx / BK, kk = idx % BK;
            As[kk][m] = A_ROW ? A[(long)(m0 + m) * lda + (k0 + kk)]
                              : A[(long)(k0 + kk) * lda + (m0 + m)];
        }
#pragma unroll
        for (int idx = tid; idx < BK * BN; idx += NTH) {
            int kk = idx / BN, n = idx % BN;
            Bs[kk][n] = B_NK ? B[(long)(n0 + n) * ldb + (k0 + kk)]
                             : B[(long)(k0 + kk) * ldb + (n0 + n)];
        }
        __syncthreads();
#pragma unroll
        for (int kk = 0; kk < BK; kk++) {
            float a[TM], bb[TN];
#pragma unroll
            for (int i = 0; i < TM; i++) a[i] = As[kk][trow * TM + i];
#pragma unroll
            for (int jx = 0; jx < TN; jx++) bb[jx] = Bs[kk][tcol * TN + jx];
#pragma unroll
            for (int i = 0; i < TM; i++)
#pragma unroll
                for (int jx = 0; jx < TN; jx++)
                    acc[i][jx] = fmaf(a[i], bb[jx], acc[i][jx]);
        }
        __syncthreads();
    }
#pragma unroll
    for (int i = 0; i < TM; i++) {
        int m = m0 + trow * TM + i;
#pragma unroll
        for (int jx = 0; jx < TN; jx++) {
            int n = n0 + tcol * TN + jx;
            float v = acc[i][jx];
            if (bias) v += bias[n];
            C[(long)m * ldc + n] = v;
        }
    }
}

// ---------------- small precompute kernels ---------------------------------
__global__ void precompC_k(const float* __restrict__ pe, const float* __restrict__ emb,
                           const float* __restrict__ W_pre, const float* __restrict__ b_pre)
{
    int t = blockIdx.x, l = threadIdx.x;
    const float* w = W_pre + l * 512;
    float acc = b_pre[l];
    for (int d = 0; d < 256; d++)
        acc += pe[t * 256 + d] * w[d] + emb[t * 256 + d] * w[256 + d];
    g_Cm[t * 256 + l] = acc;
}

__global__ void precompzW_k(const float* __restrict__ z, const float* __restrict__ W_pre)
{
    int b = blockIdx.x, l = threadIdx.x;
    const float* w = W_pre + l * 512;
    float acc = 0.f;
    for (int d = 0; d < 256; d++)
        acc += z[b * 256 + d] * w[d];
    g_zWT[l * BATCH + b] = acc;
}

__global__ void pairidx_k()
{
    int pp = blockIdx.x * blockDim.x + threadIdx.x;
    if (pp >= NPAIRS) return;
    int i = 0, rem = pp;
    while (rem >= 63 - i) { rem -= 63 - i; i++; }
    g_ii[pp] = i;
    g_jj[pp] = i + 1 + rem;
}

__global__ void zero_k(float* p, int n)
{
    int i = blockIdx.x * blockDim.x + threadIdx.x;
    if (i < n) p[i] = 0.f;
}

// ---------------- pair kernel (unchanged numerics) -------------------------
__global__ void pair_k(const float* __restrict__ W2, const float* __restrict__ b2,
                       const float* __restrict__ gu, const int* __restrict__ n_nodes,
                       float* __restrict__ out)
{
    int b    = blockIdx.x;
    int warp = (int)(blockIdx.y * 8 + (threadIdx.x >> 5));
    int lane = threadIdx.x & 31;
    int nb   = n_nodes[b];
    float* ob = out + (long)b * (MNODES * MNODES);

    float4 w2a[4], w2b[4];
#pragma unroll
    for (int q = 0; q < 4; q++) {
        w2a[q] = *(const float4*)(W2 + 4 * lane + 128 * q);
        w2b[q] = *(const float4*)(W2 + HIDDEN + 4 * lane + 128 * q);
    }
    for (int pp = warp; pp < NPAIRS; pp += 16) {
        int jn = g_jj[pp];
        if (jn >= nb) continue;
        int in = g_ii[pp];
        const float* Ui = g_U + ((long)b * MNODES + in) * HIDDEN;
        const float* Vj = g_V + ((long)b * MNODES + jn) * HIDDEN;
        float a0 = 0.f, a1 = 0.f;
#pragma unroll
        for (int q = 0; q < 4; q++) {
            float4 u = *(const float4*)(Ui + 4 * lane + 128 * q);
            float4 v = *(const float4*)(Vj + 4 * lane + 128 * q);
            float m;
            m = fmaxf(u.x + v.x, 0.f); a0 = fmaf(m, w2a[q].x, a0); a1 = fmaf(m, w2b[q].x, a1);
            m = fmaxf(u.y + v.y, 0.f); a0 = fmaf(m, w2a[q].y, a0); a1 = fmaf(m, w2b[q].y, a1);
            m = fmaxf(u.z + v.z, 0.f); a0 = fmaf(m, w2a[q].z, a0); a1 = fmaf(m, w2b[q].z, a1);
            m = fmaxf(u.w + v.w, 0.f); a0 = fmaf(m, w2a[q].w, a0); a1 = fmaf(m, w2b[q].w, a1);
        }
#pragma unroll
        for (int sft = 16; sft > 0; sft >>= 1) {
            a0 += __shfl_xor_sync(0xffffffffu, a0, sft);
            a1 += __shfl_xor_sync(0xffffffffu, a1, sft);
        }
        if (lane == 0) {
            float l0 = a0 + b2[0];
            float l1 = a1 + b2[1];
            const float* g = gu + ((long)b * NPAIRS + pp) * 2;
            float g0 = -logf(-logf(g[0] + 1e-10f) + 1e-10f);
            float g1 = -logf(-logf(g[1] + 1e-10f) + 1e-10f);
            if (l0 + g0 >= l1 + g1) {
                ob[in * MNODES + jn] = 1.f;
                ob[jn * MNODES + in] = 1.f;
            }
        }
    }
}

// ---------------- host launch sequence -------------------------------------
extern "C" void kernel_launch(void* const* d_in, const int* in_sizes, int n_in,
                              void* d_out, int out_size)
{
    const float* z       = (const float*)d_in[0];
    const int*   n_nodes = (const int*)  d_in[1];
    const float* gu      = (const float*)d_in[3];
    const float* emb     = (const float*)d_in[4];
    const float* pe      = (const float*)d_in[5];
    const float* W_pre   = (const float*)d_in[6];
    const float* b_pre   = (const float*)d_in[7];
    const float* Wih0    = (const float*)d_in[8];
    const float* Whh0    = (const float*)d_in[9];
    const float* bih0    = (const float*)d_in[10];
    const float* bhh0    = (const float*)d_in[11];
    const float* Wih1    = (const float*)d_in[12];
    const float* Whh1    = (const float*)d_in[13];
    const float* bih1    = (const float*)d_in[14];
    const float* bhh1    = (const float*)d_in[15];
    const float* node_W  = (const float*)d_in[16];
    const float* adj_W1  = (const float*)d_in[17];
    const float* adj_b1  = (const float*)d_in[18];
    const float* adj_W2  = (const float*)d_in[19];
    const float* adj_b2  = (const float*)d_in[20];
    float* out = (float*)d_out;

    float *Cm, *zWT, *AT, *D, *P, *Q, *h2T, *U, *V;
    cudaGetSymbolAddress((void**)&Cm,  g_Cm);
    cudaGetSymbolAddress((void**)&zWT, g_zWT);
    cudaGetSymbolAddress((void**)&AT,  g_AT);
    cudaGetSymbolAddress((void**)&D,   g_D);
    cudaGetSymbolAddress((void**)&P,   g_P);
    cudaGetSymbolAddress((void**)&Q,   g_Q);
    cudaGetSymbolAddress((void**)&h2T, g_h2T);
    cudaGetSymbolAddress((void**)&U,   g_U);
    cudaGetSymbolAddress((void**)&V,   g_V);

    static int smem_set = 0;
    if (!smem_set) {
        cudaFuncSetAttribute(rnn_pipe, cudaFuncAttributeMaxDynamicSharedMemorySize, 204800);
        smem_set = 1;
    }

    // --- precompute ------------------------------------------------------
    pairidx_k<<<8, 256>>>();
    precompC_k<<<MNODES, 256>>>(pe, emb, W_pre, b_pre);
    precompzW_k<<<BATCH, 256>>>(z, W_pre);

    sgemm_k<64, 32, 16, 4, 2, true, false><<<dim3(BATCH / 32, G3 / 64), 256>>>(
        Wih0, zWT, AT, nullptr, LATENT, LATENT, BATCH, BATCH, 0, 0, 0);
    sgemm_k<64, 64, 16, 4, 4, true, true><<<dim3(G3 / 64, 1), 256>>>(
        Cm, Wih0, D, nullptr, LATENT, LATENT, LATENT, G3, 0, 0, 0);
    sgemm_k<64, 64, 16, 4, 4, true, false><<<dim3(8, 8), 256>>>(
        adj_W1, node_W, P, nullptr, HIDDEN, 2 * HIDDEN, HIDDEN, HIDDEN, 0, 0, 0);
    sgemm_k<64, 64, 16, 4, 4, true, false><<<dim3(8, 8), 256>>>(
        adj_W1 + HIDDEN, node_W, Q, nullptr, HIDDEN, 2 * HIDDEN, HIDDEN, HIDDEN, 0, 0, 0);

    // --- fused pipelined recurrence (single persistent kernel) ------------
    reset_bar_k<<<1, 1>>>();
    rnn_pipe<<<128, 256, 204800>>>(Whh0, Whh1, Wih1, bih0, bhh0, bih1, bhh1, n_nodes);

    // --- U/V --------------------------------------------------------------
    sgemm_k<64, 64, 16, 4, 4, false, true><<<dim3(HIDDEN / 64, BATCH / 64, MNODES), 256>>>(
        h2T, P, U, nullptr, HIDDEN, BATCH, HIDDEN, MNODES * HIDDEN,
        (long)HB, 0, (long)HIDDEN);
    sgemm_k<64, 64, 16, 4, 4, false, true><<<dim3(HIDDEN / 64, BATCH / 64, MNODES), 256>>>(
        h2T, Q, V, adj_b1, HIDDEN, BATCH, HIDDEN, MNODES * HIDDEN,
        (long)HB, 0, (long)HIDDEN);

    // --- output ----------------------------------------------------------
    zero_k<<<(BATCH * MNODES * MNODES + 255) / 256, 256>>>(out, BATCH * MNODES * MNODES);
    pair_k<<<dim3(BATCH, 2), 256>>>(adj_W2, adj_b2, gu, n_nodes, out);
}

// round 10
// speedup vs baseline: 2.7475x; 1.2261x over previous
#include <cuda_runtime.h>
#include <math.h>

#define BATCH  128
#define LATENT 256
#define HIDDEN 512
#define MNODES 64
#define NPAIRS 2016
#define G3     1536
#define HB     65536

typedef unsigned long long u64;

// ---------------- device scratch (zero-initialized at load) ----------------
__device__ __align__(16) float g_Cm [MNODES*LATENT];
__device__ __align__(16) float g_zWT[LATENT*BATCH];
__device__ __align__(16) float g_AT [G3*BATCH];        // [g][b]
__device__ __align__(16) float g_D  [MNODES*G3];       // [t][g]
__device__ __align__(16) float g_PQt[HIDDEN*1024];     // [k][h'] P|Q transposed
__device__ __align__(16) float g_h1T[MNODES*HB];       // [t][k][b]
__device__ __align__(16) float g_h2T[MNODES*HB];       // [t][k][b]
__device__ __align__(16) float g_zH [HB];              // stays all-zero
__device__ __align__(16) float g_U  [BATCH*MNODES*HIDDEN];
__device__ __align__(16) float g_V  [BATCH*MNODES*HIDDEN];
__device__ int g_ii[NPAIRS];
__device__ int g_jj[NPAIRS];
__device__ unsigned g_bar_cnt;   // monotonic ticket counter (never reset)

// ---------------- f32x2 helpers (lanes = independent IEEE fma chains) ------
__device__ __forceinline__ u64 pack2(float x){u64 r;asm("mov.b64 %0,{%1,%1};":"=l"(r):"f"(x));return r;}
__device__ __forceinline__ void fma2(u64&a,u64 b,u64 c){asm("fma.rn.f32x2 %0, %1, %2, %0;":"+l"(a):"l"(b),"l"(c));}
__device__ __forceinline__ float2 unpk(u64 v){float2 f;asm("mov.b64 {%0,%1},%2;":"=f"(f.x),"=f"(f.y):"l"(v));return f;}
__device__ __forceinline__ u64 packab(float a,float b){u64 r;asm("mov.b64 %0,{%1,%2};":"=l"(r):"f"(a),"f"(b));return r;}
__device__ __forceinline__ float sigm(float x){return 1.f/(1.f+expf(-x));}

// ---------------- ticket grid barrier (replay-safe, no reset needed) -------
__device__ __forceinline__ void gridbar()
{
    __threadfence();
    __syncthreads();
    if (threadIdx.x == 0) {
        unsigned t = atomicAdd(&g_bar_cnt, 1u);
        unsigned target = (t & ~127u) + 128u;
        while (*(volatile unsigned*)&g_bar_cnt < target) {}
        __threadfence();
    }
    __syncthreads();
}

// ---------------- cp.async (L2-only .cg — cross-SM coherent) ---------------
__device__ __forceinline__ void cp16(void* smem, const void* gmem){
    unsigned s = (unsigned)__cvta_generic_to_shared(smem);
    asm volatile("cp.async.cg.shared.global [%0], [%1], 16;" :: "r"(s), "l"(gmem) : "memory");
}
__device__ __forceinline__ void cp_commit(){ asm volatile("cp.async.commit_group;" ::: "memory"); }
__device__ __forceinline__ void cp_wait0(){ asm volatile("cp.async.wait_group 0;" ::: "memory"); }
__device__ __forceinline__ void cp_wait1(){ asm volatile("cp.async.wait_group 1;" ::: "memory"); }
__device__ __forceinline__ void cp_wait2(){ asm volatile("cp.async.wait_group 2;" ::: "memory"); }

// ---------------- generic tiled fp32 GEMM body (ascending-k chain) ---------
template<int BM, int BN, int BK, int TM, int TN, bool A_ROW, bool B_NK>
__device__ __forceinline__ void sgemm_dev(const float* __restrict__ A, const float* __restrict__ B,
                                          float* __restrict__ C, const float* __restrict__ bias,
                                          int K, int lda, int ldb, int ldc, int m0, int n0,
                                          float* sms)
{
    float* As = sms;             // [BK][BM]
    float* Bs = sms + BM * BK;   // [BK][BN]
    constexpr int NTH = (BM / TM) * (BN / TN);
    const int tid  = threadIdx.x;
    const int tcol = tid % (BN / TN);
    const int trow = tid / (BN / TN);
    float acc[TM][TN];
#pragma unroll
    for (int i = 0; i < TM; i++)
#pragma unroll
        for (int jx = 0; jx < TN; jx++) acc[i][jx] = 0.f;
    for (int k0 = 0; k0 < K; k0 += BK) {
#pragma unroll
        for (int idx = tid; idx < BM * BK; idx += NTH) {
            int m = idx / BK, kk = idx % BK;
            As[kk*BM + m] = A_ROW ? A[(long)(m0 + m) * lda + (k0 + kk)]
                                  : A[(long)(k0 + kk) * lda + (m0 + m)];
        }
#pragma unroll
        for (int idx = tid; idx < BK * BN; idx += NTH) {
            int kk = idx / BN, n = idx % BN;
            Bs[kk*BN + n] = B_NK ? B[(long)(n0 + n) * ldb + (k0 + kk)]
                                 : B[(long)(k0 + kk) * ldb + (n0 + n)];
        }
        __syncthreads();
#pragma unroll
        for (int kk = 0; kk < BK; kk++) {
            float a[TM], bb[TN];
#pragma unroll
            for (int i = 0; i < TM; i++) a[i] = As[kk*BM + trow * TM + i];
#pragma unroll
            for (int jx = 0; jx < TN; jx++) bb[jx] = Bs[kk*BN + tcol * TN + jx];
#pragma unroll
            for (int i = 0; i < TM; i++)
#pragma unroll
                for (int jx = 0; jx < TN; jx++)
                    acc[i][jx] = fmaf(a[i], bb[jx], acc[i][jx]);
        }
        __syncthreads();
    }
#pragma unroll
    for (int i = 0; i < TM; i++) {
        int m = m0 + trow * TM + i;
#pragma unroll
        for (int jx = 0; jx < TN; jx++) {
            int n = n0 + tcol * TN + jx;
            float v = acc[i][jx];
            if (bias) v += bias[n];
            C[(long)m * ldc + n] = v;
        }
    }
}

template<int BM, int BN, int BK, int TM, int TN, bool A_ROW, bool B_NK>
__global__ void sgemm_k(const float* __restrict__ A, const float* __restrict__ B,
                        float* __restrict__ C, const float* __restrict__ bias,
                        int K, int lda, int ldb, int ldc)
{
    __shared__ float sms[BM*BK + BK*BN];
    sgemm_dev<BM,BN,BK,TM,TN,A_ROW,B_NK>(A, B, C, bias, K, lda, ldb, ldc,
                                         blockIdx.y*BM, blockIdx.x*BN, sms);
}

// ---------------- prolog fused kernel: AT + D + pairidx --------------------
// blocks 0..95: AT tiles; 96..119: D tiles; 120: pair indices.
__global__ void ATD_k(const float* __restrict__ Wih0)
{
    __shared__ float sms[2048];
    int bx = blockIdx.x;
    if (bx < 96) {
        // AT[g][b] = Wih0 @ zWT : M=1536, N=128, K=256
        sgemm_dev<64,32,16,4,2,true,false>(Wih0, g_zWT, g_AT, nullptr,
            LATENT, LATENT, BATCH, BATCH, (bx>>2)*64, (bx&3)*32, sms);
    } else if (bx < 120) {
        // D[t][g] = Cm @ Wih0^T : M=64, N=1536, K=256
        sgemm_dev<64,64,16,4,4,true,true>(g_Cm, Wih0, g_D, nullptr,
            LATENT, LATENT, LATENT, G3, 0, (bx-96)*64, sms);
    } else {
        for (int p = threadIdx.x; p < NPAIRS; p += 256) {
            int i = 0, rem = p;
            while (rem >= 63 - i) { rem -= 63 - i; i++; }
            g_ii[p] = i;
            g_jj[p] = i + 1 + rem;
        }
    }
}

// ---------------- small precompute kernels ---------------------------------
__global__ void precompC_k(const float* __restrict__ pe, const float* __restrict__ emb,
                           const float* __restrict__ W_pre, const float* __restrict__ b_pre)
{
    int t = blockIdx.x, l = threadIdx.x;
    const float* w = W_pre + l * 512;
    float acc = b_pre[l];
    for (int d = 0; d < 256; d++)
        acc += pe[t * 256 + d] * w[d] + emb[t * 256 + d] * w[256 + d];
    g_Cm[t * 256 + l] = acc;
}

__global__ void precompzW_k(const float* __restrict__ z, const float* __restrict__ W_pre)
{
    int b = blockIdx.x, l = threadIdx.x;
    const float* w = W_pre + l * 512;
    float acc = 0.f;
    for (int d = 0; d < 256; d++)
        acc += z[b * 256 + d] * w[d];
    g_zWT[l * BATCH + b] = acc;
}

__global__ void zero_k(float* p, int n)
{
    int i = blockIdx.x * blockDim.x + threadIdx.x;
    if (i < n) p[i] = 0.f;
}

// ---------------- persistent pipelined 2-layer GRU -------------------------
// 128 CTAs x 256 thr, 1 CTA/SM (200KB smem). CTA owns j rows bx*4..bx*4+3 for
// all 3 GEMMs (gh0 via Whh0, gi1 via Wih1, gh1 via Whh1). Super-step s does
// layer0 t=s and layer1 t=s-1; ONE grid barrier per step.
// Smem: 72KB packed weight pairs + 4-slot ring of 32KB h-chunks (32k x 128b x2).
__global__ void __launch_bounds__(256, 1)
rnn_pipe(const float* __restrict__ Whh0, const float* __restrict__ Whh1,
         const float* __restrict__ Wih1,
         const float* __restrict__ bih0, const float* __restrict__ bhh0,
         const float* __restrict__ bih1, const float* __restrict__ bhh1,
         const int* __restrict__ n_nodes)
{
    extern __shared__ float sm[];
    u64*   sw2  = (u64*)sm;              // 9216 u64 = 72KB
    float* ring = sm + 18432;            // 4 x 8192 floats

    const int tid = threadIdx.x;
    const int bx  = blockIdx.x;
    const int p   = tid >> 7;            // j-pair 0/1
    const int b   = tid & 127;
    const int jA  = bx*4 + 2*p;

    // stage packed weight pairs: row = (m*3+g)*2 + pr, lanes {j even, j odd}
    for (int i = tid; i < 9216; i += 256) {
        int row = i >> 9, k = i & 511;
        int mg = row >> 1, pr = row & 1;
        int m = mg / 3, g = mg % 3;
        const float* W = (m == 0) ? Whh0 : (m == 1) ? Wih1 : Whh1;
        size_t r0 = (size_t)(g*512 + bx*4 + 2*pr) * 512 + k;
        sw2[i] = packab(W[r0], W[r0 + 512]);
    }
    __syncthreads();
    const u64* w2p = sw2 + p*512;

    // per-thread constants
    float bi0[2][3], bh0[2][3], bi1[2][3], bh1[2][3], at[2][3];
#pragma unroll
    for (int l = 0; l < 2; l++) {
        int j = jA + l;
#pragma unroll
        for (int g = 0; g < 3; g++) {
            bi0[l][g] = bih0[g*512 + j]; bh0[l][g] = bhh0[g*512 + j];
            bi1[l][g] = bih1[g*512 + j]; bh1[l][g] = bhh1[g*512 + j];
            at[l][g]  = g_AT[(size_t)(g*512 + j)*128 + b];
        }
    }
    const int nn = n_nodes[b];
    float h1p[2] = {0.f, 0.f}, h2p[2] = {0.f, 0.f};

    for (int s = 0; s <= 64; s++) {
        const float* b1 = (s >= 1) ? g_h1T + (size_t)(s-1)*HB : g_zH;
        const float* b2 = (s >= 2) ? g_h2T + (size_t)(s-2)*HB : g_zH;
        u64 acc[9] = {0,0,0,0,0,0,0,0,0};

        // prime ring with chunks 0..2 (32k x 128b each, h1 + h2)
#pragma unroll
        for (int c0 = 0; c0 < 3; c0++) {
            float* buf = ring + c0*8192;
#pragma unroll
            for (int i = 0; i < 4; i++) {
                cp16(buf + (tid + 256*i)*4,        b1 + (size_t)c0*4096 + (tid + 256*i)*4);
                cp16(buf + 4096 + (tid + 256*i)*4, b2 + (size_t)c0*4096 + (tid + 256*i)*4);
            }
            cp_commit();
        }

        for (int c = 0; c < 16; c++) {
            if (c <= 13) cp_wait2(); else if (c == 14) cp_wait1(); else cp_wait0();
            __syncthreads();
            if (c + 3 < 16) {               // prefetch into slot used 4 chunks ago
                float* buf = ring + ((c+3)&3)*8192;
#pragma unroll
                for (int i = 0; i < 4; i++) {
                    cp16(buf + (tid + 256*i)*4,        b1 + (size_t)(c+3)*4096 + (tid + 256*i)*4);
                    cp16(buf + 4096 + (tid + 256*i)*4, b2 + (size_t)(c+3)*4096 + (tid + 256*i)*4);
                }
                cp_commit();
            }
            // compute 32-k chunk
            const float* sh1 = ring + (c&3)*8192;
            const float* sh2 = sh1 + 4096;
            const int kbase = c*32;
#pragma unroll 8
            for (int kk = 0; kk < 32; kk += 2) {
                ulonglong2 wv[9];
#pragma unroll
                for (int mg = 0; mg < 9; mg++)
                    wv[mg] = *(const ulonglong2*)(w2p + mg*1024 + kbase + kk);
                u64 p1a = pack2(sh1[kk*128 + b]);
                u64 p1b = pack2(sh1[(kk+1)*128 + b]);
                u64 p2a = pack2(sh2[kk*128 + b]);
                u64 p2b = pack2(sh2[(kk+1)*128 + b]);
#pragma unroll
                for (int mg = 0; mg < 6; mg++) { fma2(acc[mg], wv[mg].x, p1a); fma2(acc[mg], wv[mg].y, p1b); }
#pragma unroll
                for (int mg = 6; mg < 9; mg++) { fma2(acc[mg], wv[mg].x, p2a); fma2(acc[mg], wv[mg].y, p2b); }
            }
        }

        if (s < 64) {   // gate0, t = s
            int t = s;
            float2 vR = unpk(acc[0]), vZ = unpk(acc[1]), vN = unpk(acc[2]);
            float ghr[2]={vR.x,vR.y}, ghz[2]={vZ.x,vZ.y}, ghn[2]={vN.x,vN.y};
#pragma unroll
            for (int l = 0; l < 2; l++) {
                int j = jA + l;
                float dR = __ldg(g_D + (size_t)t*G3 + j);
                float dZ = __ldg(g_D + (size_t)t*G3 + 512 + j);
                float dN = __ldg(g_D + (size_t)t*G3 + 1024 + j);
                float gir = bi0[l][0], giz = bi0[l][1], gin = bi0[l][2];
                if (t < nn) { gir += at[l][0]+dR; giz += at[l][1]+dZ; gin += at[l][2]+dN; }
                float R = ghr[l]+bh0[l][0], Z = ghz[l]+bh0[l][1], N = ghn[l]+bh0[l][2];
                float rr = sigm(gir+R), zz = sigm(giz+Z), nl = tanhf(gin + rr*N);
                float h = (1.f - zz)*nl + zz*h1p[l];
                h1p[l] = h;
                g_h1T[(size_t)s*HB + (size_t)j*128 + b] = h;
            }
        }
        if (s >= 1) {   // gate1, t = s-1
            float2 iR = unpk(acc[3]), iZ = unpk(acc[4]), iN = unpk(acc[5]);
            float2 hR = unpk(acc[6]), hZ = unpk(acc[7]), hN = unpk(acc[8]);
            float gi_[2][3] = {{iR.x,iZ.x,iN.x},{iR.y,iZ.y,iN.y}};
            float gh_[2][3] = {{hR.x,hZ.x,hN.x},{hR.y,hZ.y,hN.y}};
#pragma unroll
            for (int l = 0; l < 2; l++) {
                int j = jA + l;
                float gir = gi_[l][0]+bi1[l][0], giz = gi_[l][1]+bi1[l][1], gin = gi_[l][2]+bi1[l][2];
                float R = gh_[l][0]+bh1[l][0], Z = gh_[l][1]+bh1[l][1], N = gh_[l][2]+bh1[l][2];
                float rr = sigm(gir+R), zz = sigm(giz+Z), nl = tanhf(gin + rr*N);
                float h = (1.f - zz)*nl + zz*h2p[l];
                h2p[l] = h;
                g_h2T[(size_t)(s-1)*HB + (size_t)j*128 + b] = h;
            }
        }
        gridbar();
    }
}

// ---------------- fused U/V GEMM (f32x2, PQt pre-packed) -------------------
// C[(t,b)][h'] = sum_k h2[t][k][b] * PQt[k][h'], h' in [0,1024).
// Grid 512 = 64 t x 8 h-chunks(128). 256 thr: thread = 4 b x 8 h-pairs.
__global__ void __launch_bounds__(256, 2)
uv_k(const float* __restrict__ adj_b1)
{
    extern __shared__ float us[];
    float* hb = us;          // 2 x 4096 (32k x 128b)
    float* wb = us + 8192;   // 2 x 4096 (32k x 128h)

    const int tid = threadIdx.x;
    const int t   = blockIdx.x >> 3;
    const int h0  = (blockIdx.x & 7) * 128;
    const int bg  = tid & 31, hg = tid >> 5;
    const int b0  = bg * 4;
    const float* hsrc = g_h2T + (size_t)t*HB;
    const float* wsrc = g_PQt + h0;

    u64 acc[8][4] = {};

#define UV_PF(c) { \
    float* hd = hb + ((c)&1)*4096; \
    float* wd = wb + ((c)&1)*4096; \
    _Pragma("unroll") for (int i = 0; i < 4; i++) { \
        int l = tid + 256*i; int row = l >> 5, c4 = l & 31; \
        cp16(hd + l*4, hsrc + (size_t)((c)*32 + row)*128  + c4*4); \
        cp16(wd + l*4, wsrc + (size_t)((c)*32 + row)*1024 + c4*4); \
    } cp_commit(); }

    UV_PF(0); UV_PF(1);
    for (int c = 0; c < 16; c++) {
        if (c < 15) cp_wait1(); else cp_wait0();
        __syncthreads();
        const float* hh = hb + (c&1)*4096;
        const float* ww = wb + (c&1)*4096;
#pragma unroll 4
        for (int kk = 0; kk < 32; kk++) {
            u64 w[8];
#pragma unroll
            for (int pp = 0; pp < 8; pp++)
                w[pp] = *(const u64*)(ww + kk*128 + hg*16 + pp*2);
            float4 hv4 = *(const float4*)(hh + kk*128 + b0);
            u64 hv[4];
            hv[0] = pack2(hv4.x); hv[1] = pack2(hv4.y);
            hv[2] = pack2(hv4.z); hv[3] = pack2(hv4.w);
#pragma unroll
            for (int pp = 0; pp < 8; pp++)
#pragma unroll
                for (int i = 0; i < 4; i++)
                    fma2(acc[pp][i], w[pp], hv[i]);
        }
        __syncthreads();
        if (c + 2 < 16) UV_PF(c + 2);
    }

#pragma unroll
    for (int pp = 0; pp < 8; pp++) {
        int hloc = h0 + hg*16 + pp*2;
#pragma unroll
        for (int i = 0; i < 4; i++) {
            float2 v = unpk(acc[pp][i]);
            int bb = b0 + i;
            if (hloc < 512) {
                *(float2*)(g_U + ((size_t)bb*64 + t)*512 + hloc) = v;
            } else {
                v.x += adj_b1[hloc - 512];
                v.y += adj_b1[hloc - 511];
                *(float2*)(g_V + ((size_t)bb*64 + t)*512 + (hloc - 512)) = v;
            }
        }
    }
}

// ---------------- pair kernel (unchanged numerics) -------------------------
__global__ void pair_k(const float* __restrict__ W2, const float* __restrict__ b2,
                       const float* __restrict__ gu, const int* __restrict__ n_nodes,
                       float* __restrict__ out)
{
    int b    = blockIdx.x;
    int warp = (int)(blockIdx.y * 8 + (threadIdx.x >> 5));
    int lane = threadIdx.x & 31;
    int nb   = n_nodes[b];
    float* ob = out + (long)b * (MNODES * MNODES);

    float4 w2a[4], w2b[4];
#pragma unroll
    for (int q = 0; q < 4; q++) {
        w2a[q] = *(const float4*)(W2 + 4 * lane + 128 * q);
        w2b[q] = *(const float4*)(W2 + HIDDEN + 4 * lane + 128 * q);
    }
    for (int pp = warp; pp < NPAIRS; pp += 16) {
        int jn = g_jj[pp];
        if (jn >= nb) continue;
        int in = g_ii[pp];
        const float* Ui = g_U + ((long)b * MNODES + in) * HIDDEN;
        const float* Vj = g_V + ((long)b * MNODES + jn) * HIDDEN;
        float a0 = 0.f, a1 = 0.f;
#pragma unroll
        for (int q = 0; q < 4; q++) {
            float4 u = *(const float4*)(Ui + 4 * lane + 128 * q);
            float4 v = *(const float4*)(Vj + 4 * lane + 128 * q);
            float m;
            m = fmaxf(u.x + v.x, 0.f); a0 = fmaf(m, w2a[q].x, a0); a1 = fmaf(m, w2b[q].x, a1);
            m = fmaxf(u.y + v.y, 0.f); a0 = fmaf(m, w2a[q].y, a0); a1 = fmaf(m, w2b[q].y, a1);
            m = fmaxf(u.z + v.z, 0.f); a0 = fmaf(m, w2a[q].z, a0); a1 = fmaf(m, w2b[q].z, a1);
            m = fmaxf(u.w + v.w, 0.f); a0 = fmaf(m, w2a[q].w, a0); a1 = fmaf(m, w2b[q].w, a1);
        }
#pragma unroll
        for (int sft = 16; sft > 0; sft >>= 1) {
            a0 += __shfl_xor_sync(0xffffffffu, a0, sft);
            a1 += __shfl_xor_sync(0xffffffffu, a1, sft);
        }
        if (lane == 0) {
            float l0 = a0 + b2[0];
            float l1 = a1 + b2[1];
            const float* g = gu + ((long)b * NPAIRS + pp) * 2;
            float g0 = -logf(-logf(g[0] + 1e-10f) + 1e-10f);
            float g1 = -logf(-logf(g[1] + 1e-10f) + 1e-10f);
            if (l0 + g0 >= l1 + g1) {
                ob[in * MNODES + jn] = 1.f;
                ob[jn * MNODES + in] = 1.f;
            }
        }
    }
}

// ---------------- host launch sequence -------------------------------------
extern "C" void kernel_launch(void* const* d_in, const int* in_sizes, int n_in,
                              void* d_out, int out_size)
{
    const float* z       = (const float*)d_in[0];
    const int*   n_nodes = (const int*)  d_in[1];
    const float* gu      = (const float*)d_in[3];
    const float* emb     = (const float*)d_in[4];
    const float* pe      = (const float*)d_in[5];
    const float* W_pre   = (const float*)d_in[6];
    const float* b_pre   = (const float*)d_in[7];
    const float* Wih0    = (const float*)d_in[8];
    const float* Whh0    = (const float*)d_in[9];
    const float* bih0    = (const float*)d_in[10];
    const float* bhh0    = (const float*)d_in[11];
    const float* Wih1    = (const float*)d_in[12];
    const float* Whh1    = (const float*)d_in[13];
    const float* bih1    = (const float*)d_in[14];
    const float* bhh1    = (const float*)d_in[15];
    const float* node_W  = (const float*)d_in[16];
    const float* adj_W1  = (const float*)d_in[17];
    const float* adj_b1  = (const float*)d_in[18];
    const float* adj_W2  = (const float*)d_in[19];
    const float* adj_b2  = (const float*)d_in[20];
    float* out = (float*)d_out;

    float *PQt;
    cudaGetSymbolAddress((void**)&PQt, g_PQt);

    static int attr_set = 0;
    if (!attr_set) {
        cudaFuncSetAttribute(rnn_pipe, cudaFuncAttributeMaxDynamicSharedMemorySize, 204800);
        cudaFuncSetAttribute(uv_k,     cudaFuncAttributeMaxDynamicSharedMemorySize, 65536);
        attr_set = 1;
    }

    // 1-3: prolog (positions rnn_pipe as 4th launch for ncu -s capture)
    precompC_k<<<MNODES, 256>>>(pe, emb, W_pre, b_pre);
    precompzW_k<<<BATCH, 256>>>(z, W_pre);
    ATD_k<<<121, 256>>>(Wih0);

    // 4: fused pipelined recurrence (persistent)
    rnn_pipe<<<128, 256, 204800>>>(Whh0, Whh1, Wih1, bih0, bhh0, bih1, bhh1, n_nodes);

    // 5-6: PQt[k][h'] = P^T | Q^T  (same ascending-d fmaf chain as before)
    sgemm_k<64, 64, 16, 4, 4, false, true><<<dim3(8, 8), 256>>>(
        node_W, adj_W1, PQt, nullptr, HIDDEN, HIDDEN, 2 * HIDDEN, 1024);
    sgemm_k<64, 64, 16, 4, 4, false, true><<<dim3(8, 8), 256>>>(
        node_W, adj_W1 + HIDDEN, PQt + 512, nullptr, HIDDEN, HIDDEN, 2 * HIDDEN, 1024);

    // 7: fused U/V
    uv_k<<<512, 256, 65536>>>(adj_b1);

    // 8-9: output
    zero_k<<<(BATCH * MNODES * MNODES + 255) / 256, 256>>>(out, BATCH * MNODES * MNODES);
    pair_k<<<dim3(BATCH, 2), 256>>>(adj_W2, adj_b2, gu, n_nodes, out);
}